// round 3
// baseline (speedup 1.0000x reference)
#include <cuda_runtime.h>
#include <cuda_bf16.h>
#include <cstdint>

// FlashAttention B=2,H=16,S=4096,D=64 fp32, non-causal.
// Reference's exact recurrence (block_max variant), BN=128 fixed, in order.
// Tensor-core path: mma.sync m16n8k16 bf16, 3-term hi/lo split (~fp32 accuracy).

#define SEQ   4096
#define HD    64
#define BM    128
#define BN    128
#define NTHR  256
#define NBLK  (SEQ / BN)        // 32
#define SCALE 0.125f

#define NTOT  (2 * 16 * SEQ * HD)   // 8388608 elems per tensor

// bf16 hi/lo scratch (static device arrays: allocation-free)
__device__ __nv_bfloat16 g_qh[NTOT];
__device__ __nv_bfloat16 g_ql[NTOT];
__device__ __nv_bfloat16 g_kh[NTOT];
__device__ __nv_bfloat16 g_kl[NTOT];
__device__ __nv_bfloat16 g_vh[NTOT];
__device__ __nv_bfloat16 g_vl[NTOT];

// ---------------- converter: fp32 -> bf16 hi/lo ----------------
__device__ __forceinline__ void split4(float4 t, float s,
                                       __nv_bfloat16* hp, __nv_bfloat16* lp)
{
    float x0 = t.x * s, x1 = t.y * s, x2 = t.z * s, x3 = t.w * s;
    __nv_bfloat16 h0 = __float2bfloat16_rn(x0);
    __nv_bfloat16 h1 = __float2bfloat16_rn(x1);
    __nv_bfloat16 h2 = __float2bfloat16_rn(x2);
    __nv_bfloat16 h3 = __float2bfloat16_rn(x3);
    __nv_bfloat16 l0 = __float2bfloat16_rn(x0 - __bfloat162float(h0));
    __nv_bfloat16 l1 = __float2bfloat16_rn(x1 - __bfloat162float(h1));
    __nv_bfloat16 l2 = __float2bfloat16_rn(x2 - __bfloat162float(h2));
    __nv_bfloat16 l3 = __float2bfloat16_rn(x3 - __bfloat162float(h3));
    __nv_bfloat162 hA; hA.x = h0; hA.y = h1;
    __nv_bfloat162 hB; hB.x = h2; hB.y = h3;
    __nv_bfloat162 lA; lA.x = l0; lA.y = l1;
    __nv_bfloat162 lB; lB.x = l2; lB.y = l3;
    uint2 hu = make_uint2(*(uint32_t*)&hA, *(uint32_t*)&hB);
    uint2 lu = make_uint2(*(uint32_t*)&lA, *(uint32_t*)&lB);
    *(uint2*)hp = hu;
    *(uint2*)lp = lu;
}

__global__ __launch_bounds__(512)
void cvt_kernel(const float* __restrict__ q,
                const float* __restrict__ k,
                const float* __restrict__ v)
{
    int i = blockIdx.x * blockDim.x + threadIdx.x;   // one float4 group
    if (i >= NTOT / 4) return;
    split4(((const float4*)q)[i], SCALE, g_qh + 4 * i, g_ql + 4 * i);
    split4(((const float4*)k)[i], 1.0f,  g_kh + 4 * i, g_kl + 4 * i);
    split4(((const float4*)v)[i], 1.0f,  g_vh + 4 * i, g_vl + 4 * i);
}

// ---------------- main attention kernel ----------------
// smem (bf16 elems): Qh[128*64], Ql[128*64], then 2 stages of
// {Kh,Kl,Vh,Vl}[128*64] each.
#define TILE_E   (BM * HD)                 // 8192 bf16 = 16KB
#define OFF_QH   0
#define OFF_QL   TILE_E
#define OFF_ST0  (2 * TILE_E)
#define STAGE_E  (4 * TILE_E)
#define SMEM_BYTES ((2 * TILE_E + 2 * STAGE_E) * 2)   // 163840

// swizzled byte offset of 16B chunk (row in [0,128), chunk in [0,8))
__device__ __forceinline__ uint32_t swz(uint32_t row, uint32_t ch)
{
    return (row * 8u + (ch ^ (row & 7u))) * 16u;
}

__device__ __forceinline__ void cp16(uint32_t dst, const void* src)
{
    asm volatile("cp.async.cg.shared.global [%0], [%1], 16;\n"
                 :: "r"(dst), "l"(src));
}
__device__ __forceinline__ void cp_commit()
{
    asm volatile("cp.async.commit_group;\n");
}
__device__ __forceinline__ void cp_wait1()
{
    asm volatile("cp.async.wait_group 1;\n");
}
__device__ __forceinline__ void cp_wait0()
{
    asm volatile("cp.async.wait_group 0;\n");
}

__device__ __forceinline__ void ldm_x4(uint32_t a, uint32_t& r0, uint32_t& r1,
                                       uint32_t& r2, uint32_t& r3)
{
    asm volatile("ldmatrix.sync.aligned.m8n8.x4.shared.b16 {%0,%1,%2,%3}, [%4];\n"
                 : "=r"(r0), "=r"(r1), "=r"(r2), "=r"(r3) : "r"(a));
}
__device__ __forceinline__ void ldm_x2(uint32_t a, uint32_t& r0, uint32_t& r1)
{
    asm volatile("ldmatrix.sync.aligned.m8n8.x2.shared.b16 {%0,%1}, [%2];\n"
                 : "=r"(r0), "=r"(r1) : "r"(a));
}
__device__ __forceinline__ void ldm_x2t(uint32_t a, uint32_t& r0, uint32_t& r1)
{
    asm volatile("ldmatrix.sync.aligned.m8n8.x2.trans.shared.b16 {%0,%1}, [%2];\n"
                 : "=r"(r0), "=r"(r1) : "r"(a));
}

__device__ __forceinline__ void mma_bf16(float* c, const uint32_t* a,
                                         const uint32_t* b)
{
    asm volatile(
        "mma.sync.aligned.m16n8k16.row.col.f32.bf16.bf16.f32 "
        "{%0,%1,%2,%3}, {%4,%5,%6,%7}, {%8,%9}, {%0,%1,%2,%3};\n"
        : "+f"(c[0]), "+f"(c[1]), "+f"(c[2]), "+f"(c[3])
        : "r"(a[0]), "r"(a[1]), "r"(a[2]), "r"(a[3]), "r"(b[0]), "r"(b[1]));
}

__device__ __forceinline__ uint32_t pack2(float a, float b)
{
    __nv_bfloat162 t;
    t.x = __float2bfloat16_rn(a);
    t.y = __float2bfloat16_rn(b);
    return *(uint32_t*)&t;
}

__global__ __launch_bounds__(NTHR, 1)
void fa2_kernel(float* __restrict__ out)
{
    extern __shared__ __align__(16) unsigned char smraw[];
    uint32_t sbase = (uint32_t)__cvta_generic_to_shared(smraw);

    const int tid  = threadIdx.x;
    const int lane = tid & 31;
    const int w    = tid >> 5;          // warp 0..7 -> rows w*16..w*16+15
    const int bh   = blockIdx.y;
    const int qb   = blockIdx.x;

    const uint32_t qsmh = sbase + OFF_QH * 2;
    const uint32_t qsml = sbase + OFF_QL * 2;

    // ---- stage Q (hi/lo) into swizzled smem ----
    {
        const __nv_bfloat16* qh = g_qh + ((size_t)bh * SEQ + (size_t)qb * BM) * HD;
        const __nv_bfloat16* ql = g_ql + ((size_t)bh * SEQ + (size_t)qb * BM) * HD;
        #pragma unroll
        for (int i = 0; i < 4; i++) {
            int cid = tid + i * NTHR;        // 0..1023
            int row = cid >> 3, ch = cid & 7;
            uint32_t d = swz(row, ch);
            *(uint4*)(smraw + OFF_QH * 2 + d) = *(const uint4*)(qh + row * HD + ch * 8);
            *(uint4*)(smraw + OFF_QL * 2 + d) = *(const uint4*)(ql + row * HD + ch * 8);
        }
    }

    // ---- issue cp.async for K/V blocks 0 and 1 ----
    const size_t kvbase = (size_t)bh * SEQ * HD;
    auto stage_load = [&](int blk) {
        int st = blk & 1;
        uint32_t sb = sbase + (OFF_ST0 + st * STAGE_E) * 2;
        size_t gb = kvbase + (size_t)blk * BN * HD;
        #pragma unroll
        for (int i = 0; i < 4; i++) {
            int cid = tid + i * NTHR;
            int row = cid >> 3, ch = cid & 7;
            uint32_t d = swz(row, ch);
            size_t g = gb + (size_t)row * HD + ch * 8;
            cp16(sb + 0 * TILE_E * 2 + d, g_kh + g);
            cp16(sb + 1 * TILE_E * 2 + d, g_kl + g);
            cp16(sb + 2 * TILE_E * 2 + d, g_vh + g);
            cp16(sb + 3 * TILE_E * 2 + d, g_vl + g);
        }
        cp_commit();
    };
    stage_load(0);
    stage_load(1);

    __syncthreads();   // Q smem visible

    // ---- load Q fragments (held in registers for all 32 blocks) ----
    uint32_t qfh[4][4], qfl[4][4];
    {
        int quad = lane >> 3, i = lane & 7;
        int row = w * 16 + (quad & 1) * 8 + i;
        #pragma unroll
        for (int t = 0; t < 4; t++) {
            uint32_t a = swz(row, 2 * t + (quad >> 1));
            ldm_x4(qsmh + a, qfh[t][0], qfh[t][1], qfh[t][2], qfh[t][3]);
            ldm_x4(qsml + a, qfl[t][0], qfl[t][1], qfl[t][2], qfl[t][3]);
        }
    }

    float o[8][4];
    #pragma unroll
    for (int n = 0; n < 8; n++)
        #pragma unroll
        for (int r = 0; r < 4; r++) o[n][r] = 0.f;
    float m0 = -1e30f, m1 = -1e30f, nr0 = 0.f, nr1 = 0.f;

    const int li = lane & 15;

    for (int blk = 0; blk < NBLK; blk++) {
        if (blk < NBLK - 2) cp_wait1(); else cp_wait0();
        __syncthreads();

        int st = blk & 1;
        uint32_t kh_b = sbase + (OFF_ST0 + st * STAGE_E + 0 * TILE_E) * 2;
        uint32_t kl_b = sbase + (OFF_ST0 + st * STAGE_E + 1 * TILE_E) * 2;
        uint32_t vh_b = sbase + (OFF_ST0 + st * STAGE_E + 2 * TILE_E) * 2;
        uint32_t vl_b = sbase + (OFF_ST0 + st * STAGE_E + 3 * TILE_E) * 2;

        // ---- QK^T: scores c[16 n-tiles][4] ----
        float c[16][4];
        #pragma unroll
        for (int j = 0; j < 16; j++) {
            c[j][0] = c[j][1] = c[j][2] = c[j][3] = 0.f;
            int row = 8 * j + (li & 7);
            #pragma unroll
            for (int t = 0; t < 4; t++) {
                uint32_t a = swz(row, 2 * t + (li >> 3));
                uint32_t bh2[2], bl2[2];
                ldm_x2(kh_b + a, bh2[0], bh2[1]);
                ldm_x2(kl_b + a, bl2[0], bl2[1]);
                mma_bf16(c[j], qfh[t], bh2);
                mma_bf16(c[j], qfh[t], bl2);
                mma_bf16(c[j], qfl[t], bh2);
            }
        }

        // ---- online softmax (reference recurrence, block max) ----
        float mx0 = -1e30f, mx1 = -1e30f;
        #pragma unroll
        for (int j = 0; j < 16; j++) {
            mx0 = fmaxf(mx0, fmaxf(c[j][0], c[j][1]));
            mx1 = fmaxf(mx1, fmaxf(c[j][2], c[j][3]));
        }
        mx0 = fmaxf(mx0, __shfl_xor_sync(0xffffffffu, mx0, 1));
        mx0 = fmaxf(mx0, __shfl_xor_sync(0xffffffffu, mx0, 2));
        mx1 = fmaxf(mx1, __shfl_xor_sync(0xffffffffu, mx1, 1));
        mx1 = fmaxf(mx1, __shfl_xor_sync(0xffffffffu, mx1, 2));

        float nm0 = fmaxf(m0, mx0), nm1 = fmaxf(m1, mx1);
        float e0 = __expf(m0 - nm0), e1 = __expf(m1 - nm1);
        m0 = nm0; m1 = nm1;

        float rs0 = 0.f, rs1 = 0.f;
        #pragma unroll
        for (int j = 0; j < 16; j++) {
            c[j][0] = __expf(c[j][0] - mx0);
            c[j][1] = __expf(c[j][1] - mx0);
            c[j][2] = __expf(c[j][2] - mx1);
            c[j][3] = __expf(c[j][3] - mx1);
            rs0 += c[j][0] + c[j][1];
            rs1 += c[j][2] + c[j][3];
        }
        rs0 += __shfl_xor_sync(0xffffffffu, rs0, 1);
        rs0 += __shfl_xor_sync(0xffffffffu, rs0, 2);
        rs1 += __shfl_xor_sync(0xffffffffu, rs1, 1);
        rs1 += __shfl_xor_sync(0xffffffffu, rs1, 2);
        nr0 = nr0 * e0 + rs0;
        nr1 = nr1 * e1 + rs1;

        #pragma unroll
        for (int n = 0; n < 8; n++) {
            o[n][0] *= e0; o[n][1] *= e0;
            o[n][2] *= e1; o[n][3] *= e1;
        }

        // ---- PV: o += exp_scores @ V (P hi/lo in regs from C frags) ----
        #pragma unroll
        for (int t = 0; t < 8; t++) {       // k-tile: keys 16t..16t+15
            uint32_t pah[4], pal[4];
            #pragma unroll
            for (int h = 0; h < 2; h++) {   // sub n-tile 2t+h
                int j = 2 * t + h;
                float x0 = c[j][0], x1 = c[j][1], x2 = c[j][2], x3 = c[j][3];
                uint32_t h01 = pack2(x0, x1);
                uint32_t h23 = pack2(x2, x3);
                __nv_bfloat162 hv01 = *(__nv_bfloat162*)&h01;
                __nv_bfloat162 hv23 = *(__nv_bfloat162*)&h23;
                pah[2 * h + 0] = h01;
                pah[2 * h + 1] = h23;
                pal[2 * h + 0] = pack2(x0 - __bfloat162float(hv01.x),
                                       x1 - __bfloat162float(hv01.y));
                pal[2 * h + 1] = pack2(x2 - __bfloat162float(hv23.x),
                                       x3 - __bfloat162float(hv23.y));
            }
            // hmm: A-frag order is a0=(r,k0..),a1=(r+8,k0..),a2=(r,k8..),a3=(r+8,k8..)
            // built above as [j=2t: a0,a1][j=2t+1: a2,a3] -> correct.
            int vrow = 16 * t + li;
            #pragma unroll
            for (int n = 0; n < 8; n++) {   // d-tile
                uint32_t a = swz(vrow, n ^ (vrow & 7));
                // note swz takes (row, logical ch); inline XOR here:
                a = (vrow * 8u + ((uint32_t)n ^ (vrow & 7u))) * 16u;
                uint32_t bvh[2], bvl[2];
                ldm_x2t(vh_b + a, bvh[0], bvh[1]);
                ldm_x2t(vl_b + a, bvl[0], bvl[1]);
                mma_bf16(o[n], pah, bvh);
                mma_bf16(o[n], pah, bvl);
                mma_bf16(o[n], pal, bvh);
            }
        }

        __syncthreads();                    // all warps done with stage st
        if (blk + 2 < NBLK) stage_load(blk + 2);
    }

    // ---- epilogue ----
    float inv0 = 1.f / (nr0 + 1e-6f);
    float inv1 = 1.f / (nr1 + 1e-6f);
    int r  = lane >> 2;
    int cb = (lane & 3) * 2;
    float* og0 = out + ((size_t)bh * SEQ + (size_t)qb * BM + w * 16 + r) * HD;
    float* og1 = og0 + 8 * HD;
    #pragma unroll
    for (int n = 0; n < 8; n++) {
        *(float2*)(og0 + n * 8 + cb) = make_float2(o[n][0] * inv0, o[n][1] * inv0);
        *(float2*)(og1 + n * 8 + cb) = make_float2(o[n][2] * inv1, o[n][3] * inv1);
    }
}

extern "C" void kernel_launch(void* const* d_in, const int* in_sizes, int n_in,
                              void* d_out, int out_size)
{
    const float* q = (const float*)d_in[0];
    const float* k = (const float*)d_in[1];
    const float* v = (const float*)d_in[2];
    float* o = (float*)d_out;

    int n_bh = in_sizes[0] / (SEQ * HD);    // 32

    cudaFuncSetAttribute(fa2_kernel, cudaFuncAttributeMaxDynamicSharedMemorySize,
                         SMEM_BYTES);

    cvt_kernel<<<(NTOT / 4 + 511) / 512, 512>>>(q, k, v);
    dim3 grid(SEQ / BM, n_bh);
    fa2_kernel<<<grid, NTHR, SMEM_BYTES>>>(o);
}

// round 5
// speedup vs baseline: 1.0299x; 1.0299x over previous
#include <cuda_runtime.h>
#include <cuda_bf16.h>
#include <cstdint>

// FlashAttention B=2,H=16,S=4096,D=64 fp32, non-causal.
// Reference's exact recurrence (block_max variant), BN=128 fixed, in order.
// mma.sync m16n8k16 bf16, 3-term hi/lo split (~fp32 accuracy), exp2 domain.
// BM=64 / 128 threads / 112KB smem -> 2 CTAs per SM for cross-CTA overlap.

#define SEQ   4096
#define HD    64
#define BM    64
#define BN    128
#define NTHR  128
#define NBLK  (SEQ / BN)
// (1/sqrt(64)) * log2(e): scores land in log2 domain, exp := ex2.approx
#define SCL2E 0.18033688011112042f

#define NTOT  (2 * 16 * SEQ * HD)

__device__ __nv_bfloat16 g_qh[NTOT];
__device__ __nv_bfloat16 g_ql[NTOT];
__device__ __nv_bfloat16 g_kh[NTOT];
__device__ __nv_bfloat16 g_kl[NTOT];
__device__ __nv_bfloat16 g_vh[NTOT];
__device__ __nv_bfloat16 g_vl[NTOT];

// ---------------- converter: fp32 -> bf16 hi/lo ----------------
__device__ __forceinline__ void split4(float4 t, float s,
                                       __nv_bfloat16* hp, __nv_bfloat16* lp)
{
    float x0 = t.x * s, x1 = t.y * s, x2 = t.z * s, x3 = t.w * s;
    __nv_bfloat16 h0 = __float2bfloat16_rn(x0);
    __nv_bfloat16 h1 = __float2bfloat16_rn(x1);
    __nv_bfloat16 h2 = __float2bfloat16_rn(x2);
    __nv_bfloat16 h3 = __float2bfloat16_rn(x3);
    __nv_bfloat16 l0 = __float2bfloat16_rn(x0 - __bfloat162float(h0));
    __nv_bfloat16 l1 = __float2bfloat16_rn(x1 - __bfloat162float(h1));
    __nv_bfloat16 l2 = __float2bfloat16_rn(x2 - __bfloat162float(h2));
    __nv_bfloat16 l3 = __float2bfloat16_rn(x3 - __bfloat162float(h3));
    __nv_bfloat162 hA; hA.x = h0; hA.y = h1;
    __nv_bfloat162 hB; hB.x = h2; hB.y = h3;
    __nv_bfloat162 lA; lA.x = l0; lA.y = l1;
    __nv_bfloat162 lB; lB.x = l2; lB.y = l3;
    *(uint2*)hp = make_uint2(*(uint32_t*)&hA, *(uint32_t*)&hB);
    *(uint2*)lp = make_uint2(*(uint32_t*)&lA, *(uint32_t*)&lB);
}

__global__ __launch_bounds__(512)
void cvt_kernel(const float* __restrict__ q,
                const float* __restrict__ k,
                const float* __restrict__ v)
{
    int i = blockIdx.x * blockDim.x + threadIdx.x;
    if (i >= NTOT / 4) return;
    split4(((const float4*)q)[i], SCL2E, g_qh + 4 * i, g_ql + 4 * i);
    split4(((const float4*)k)[i], 1.0f,  g_kh + 4 * i, g_kl + 4 * i);
    split4(((const float4*)v)[i], 1.0f,  g_vh + 4 * i, g_vl + 4 * i);
}

// ---------------- smem layout (byte offsets) ----------------
#define O_QH   0
#define O_QL   8192
#define O_K0   16384          // stage st: Kh at O_K0+st*32768, Kl at +16384
#define O_VH   81920
#define O_VL   98304
#define SMEM_BYTES 114688     // 112KB -> 2 CTAs/SM

// swizzled byte offset of a 16B chunk (row, chunk in [0,8))
__device__ __forceinline__ uint32_t swz(uint32_t row, uint32_t ch)
{
    return (row * 8u + (ch ^ (row & 7u))) * 16u;
}

__device__ __forceinline__ void cp16(uint32_t dst, const void* src)
{
    asm volatile("cp.async.cg.shared.global [%0], [%1], 16;" :: "r"(dst), "l"(src));
}
__device__ __forceinline__ void cp_commit() { asm volatile("cp.async.commit_group;"); }
__device__ __forceinline__ void cp_wait0()  { asm volatile("cp.async.wait_group 0;"); }
__device__ __forceinline__ void cp_wait1()  { asm volatile("cp.async.wait_group 1;"); }

__device__ __forceinline__ void ldm_x4(uint32_t a, uint32_t* r)
{
    asm volatile("ldmatrix.sync.aligned.m8n8.x4.shared.b16 {%0,%1,%2,%3}, [%4];"
                 : "=r"(r[0]), "=r"(r[1]), "=r"(r[2]), "=r"(r[3]) : "r"(a));
}
__device__ __forceinline__ void ldm_x4t(uint32_t a, uint32_t* r)
{
    asm volatile("ldmatrix.sync.aligned.m8n8.x4.trans.shared.b16 {%0,%1,%2,%3}, [%4];"
                 : "=r"(r[0]), "=r"(r[1]), "=r"(r[2]), "=r"(r[3]) : "r"(a));
}
__device__ __forceinline__ void mma_bf16(float* c, const uint32_t* a,
                                         const uint32_t* b)
{
    asm volatile(
        "mma.sync.aligned.m16n8k16.row.col.f32.bf16.bf16.f32 "
        "{%0,%1,%2,%3}, {%4,%5,%6,%7}, {%8,%9}, {%0,%1,%2,%3};"
        : "+f"(c[0]), "+f"(c[1]), "+f"(c[2]), "+f"(c[3])
        : "r"(a[0]), "r"(a[1]), "r"(a[2]), "r"(a[3]), "r"(b[0]), "r"(b[1]));
}
__device__ __forceinline__ uint32_t pack2(float a, float b)
{
    __nv_bfloat162 t;
    t.x = __float2bfloat16_rn(a);
    t.y = __float2bfloat16_rn(b);
    return *(uint32_t*)&t;
}
__device__ __forceinline__ float ex2f(float x)
{
    float r; asm("ex2.approx.f32 %0, %1;" : "=f"(r) : "f"(x)); return r;
}

__global__ __launch_bounds__(NTHR, 2)
void fa4_kernel(float* __restrict__ out)
{
    extern __shared__ __align__(16) unsigned char smraw[];
    uint32_t sb = (uint32_t)__cvta_generic_to_shared(smraw);

    const int tid  = threadIdx.x;
    const int lane = tid & 31;
    const int w    = tid >> 5;          // 4 warps, rows w*16..w*16+15
    const int bh   = blockIdx.y;
    const int qb   = blockIdx.x;

    // ---- prologue cp.async: group P0={Q,K0,V0}, group P1={K1} ----
    const size_t kvbase = (size_t)bh * SEQ * HD;
    {
        const __nv_bfloat16* qh = g_qh + ((size_t)bh * SEQ + (size_t)qb * BM) * HD;
        const __nv_bfloat16* ql = g_ql + ((size_t)bh * SEQ + (size_t)qb * BM) * HD;
        #pragma unroll
        for (int i = 0; i < 4; i++) {           // 512 chunks (Q tile 8KB)
            int c = tid + i * NTHR;
            uint32_t d = swz(c >> 3, c & 7);
            const size_t g = (size_t)(c >> 3) * HD + (c & 7) * 8;
            cp16(sb + O_QH + d, qh + g);
            cp16(sb + O_QL + d, ql + g);
        }
    }
    auto tile_ld = [&](uint32_t dstb, const __nv_bfloat16* src) {
        #pragma unroll
        for (int i = 0; i < 8; i++) {           // 1024 chunks (16KB tile)
            int c = tid + i * NTHR;
            cp16(dstb + swz(c >> 3, c & 7), src + (size_t)(c >> 3) * HD + (c & 7) * 8);
        }
    };
    auto load_K = [&](int i) {
        size_t g = kvbase + (size_t)i * BN * HD;
        uint32_t ks = sb + O_K0 + (i & 1) * 32768;
        tile_ld(ks,         g_kh + g);
        tile_ld(ks + 16384, g_kl + g);
    };
    auto load_V = [&](int i) {
        size_t g = kvbase + (size_t)i * BN * HD;
        tile_ld(sb + O_VH, g_vh + g);
        tile_ld(sb + O_VL, g_vl + g);
    };
    load_K(0); load_V(0); cp_commit();          // P0 (with Q)
    load_K(1); cp_commit();                     // P1

    cp_wait1();                                 // P0 complete (Q,K0,V0)
    __syncthreads();

    // ---- persistent Q fragments ----
    uint32_t qfh[4][4], qfl[4][4];
    {
        int quad = lane >> 3, i = lane & 7;
        int row = w * 16 + (quad & 1) * 8 + i;
        #pragma unroll
        for (int t = 0; t < 4; t++) {
            uint32_t a = swz(row, 2 * t + (quad >> 1));
            ldm_x4(sb + O_QH + a, qfh[t]);
            ldm_x4(sb + O_QL + a, qfl[t]);
        }
    }

    float o[8][4];
    #pragma unroll
    for (int n = 0; n < 8; n++)
        #pragma unroll
        for (int r = 0; r < 4; r++) o[n][r] = 0.f;
    float m0 = -1e30f, m1 = -1e30f, nr0 = 0.f, nr1 = 0.f;

    for (int blk = 0; blk < NBLK; blk++) {
        if (blk >= NBLK - 2) cp_wait0(); else cp_wait1();
        __syncthreads();                         // K(blk), V(blk) visible

        uint32_t kh_b = sb + O_K0 + (blk & 1) * 32768;

        // ---- QK^T: 3-term bf16, ldmatrix.x4 over n-tile pairs ----
        float c[16][4];
        const int rowB = (lane & 7) + ((lane >> 4) << 3);
        const int chB  = (lane >> 3) & 1;
        #pragma unroll
        for (int j2 = 0; j2 < 8; j2++) {
            c[2*j2][0] = c[2*j2][1] = c[2*j2][2] = c[2*j2][3] = 0.f;
            c[2*j2+1][0] = c[2*j2+1][1] = c[2*j2+1][2] = c[2*j2+1][3] = 0.f;
            int row = 16 * j2 + rowB;
            #pragma unroll
            for (int t = 0; t < 4; t++) {
                uint32_t a = kh_b + swz(row, 2 * t + chB);
                uint32_t b4h[4], b4l[4];
                ldm_x4(a, b4h);
                ldm_x4(a + 16384, b4l);
                mma_bf16(c[2*j2],   qfh[t], b4h);
                mma_bf16(c[2*j2],   qfh[t], b4l);
                mma_bf16(c[2*j2],   qfl[t], b4h);
                mma_bf16(c[2*j2+1], qfh[t], b4h + 2);
                mma_bf16(c[2*j2+1], qfh[t], b4l + 2);
                mma_bf16(c[2*j2+1], qfl[t], b4h + 2);
            }
        }

        // ---- block max (reference recurrence, log2 domain) ----
        float mx0 = -1e30f, mx1 = -1e30f;
        #pragma unroll
        for (int j = 0; j < 16; j++) {
            mx0 = fmaxf(mx0, fmaxf(c[j][0], c[j][1]));
            mx1 = fmaxf(mx1, fmaxf(c[j][2], c[j][3]));
        }
        mx0 = fmaxf(mx0, __shfl_xor_sync(0xffffffffu, mx0, 1));
        mx0 = fmaxf(mx0, __shfl_xor_sync(0xffffffffu, mx0, 2));
        mx1 = fmaxf(mx1, __shfl_xor_sync(0xffffffffu, mx1, 1));
        mx1 = fmaxf(mx1, __shfl_xor_sync(0xffffffffu, mx1, 2));

        float nm0 = fmaxf(m0, mx0), nm1 = fmaxf(m1, mx1);
        float e0 = ex2f(m0 - nm0), e1 = ex2f(m1 - nm1);
        m0 = nm0; m1 = nm1;
        #pragma unroll
        for (int n = 0; n < 8; n++) {
            o[n][0] *= e0; o[n][1] *= e0;
            o[n][2] *= e1; o[n][3] *= e1;
        }

        // ---- chunked exp + pack + PV (overlaps MUFU/pack with HMMA) ----
        float rs0 = 0.f, rs1 = 0.f;
        const int vri = lane & 15;
        const int vch = lane >> 4;
        #pragma unroll
        for (int t = 0; t < 8; t++) {
            uint32_t pah[4], pal[4];
            #pragma unroll
            for (int h = 0; h < 2; h++) {
                int j = 2 * t + h;
                float x0 = ex2f(c[j][0] - mx0);
                float x1 = ex2f(c[j][1] - mx0);
                float x2 = ex2f(c[j][2] - mx1);
                float x3 = ex2f(c[j][3] - mx1);
                rs0 += x0 + x1;
                rs1 += x2 + x3;
                uint32_t h01 = pack2(x0, x1);
                uint32_t h23 = pack2(x2, x3);
                float h0 = __uint_as_float(h01 << 16);
                float h1 = __uint_as_float(h01 & 0xffff0000u);
                float h2 = __uint_as_float(h23 << 16);
                float h3 = __uint_as_float(h23 & 0xffff0000u);
                pah[2*h]   = h01;
                pah[2*h+1] = h23;
                pal[2*h]   = pack2(x0 - h0, x1 - h1);
                pal[2*h+1] = pack2(x2 - h2, x3 - h3);
            }
            int vrow = 16 * t + vri;
            #pragma unroll
            for (int np = 0; np < 4; np++) {
                uint32_t a = sb + O_VH + swz(vrow, 2 * np + vch);
                uint32_t v4h[4], v4l[4];
                ldm_x4t(a, v4h);
                ldm_x4t(a + 16384, v4l);
                mma_bf16(o[2*np],   pah, v4h);
                mma_bf16(o[2*np],   pah, v4l);
                mma_bf16(o[2*np],   pal, v4h);
                mma_bf16(o[2*np+1], pah, v4h + 2);
                mma_bf16(o[2*np+1], pah, v4l + 2);
                mma_bf16(o[2*np+1], pal, v4h + 2);
            }
        }
        rs0 += __shfl_xor_sync(0xffffffffu, rs0, 1);
        rs0 += __shfl_xor_sync(0xffffffffu, rs0, 2);
        rs1 += __shfl_xor_sync(0xffffffffu, rs1, 1);
        rs1 += __shfl_xor_sync(0xffffffffu, rs1, 2);
        nr0 = nr0 * e0 + rs0;
        nr1 = nr1 * e1 + rs1;

        // ---- prefetch: V(blk+1) [group A], K(blk+2) [group B] ----
        __syncthreads();                 // everyone done reading V / K stage
        if (blk + 1 < NBLK) load_V(blk + 1);
        cp_commit();                     // A_blk (always committed)
        if (blk + 2 < NBLK) load_K(blk + 2);
        cp_commit();                     // B_blk (always committed)
    }

    // ---- epilogue ----
    float inv0 = 1.f / (nr0 + 1e-6f);
    float inv1 = 1.f / (nr1 + 1e-6f);
    int r  = lane >> 2;
    int cb = (lane & 3) * 2;
    float* og0 = out + ((size_t)bh * SEQ + (size_t)qb * BM + w * 16 + r) * HD;
    float* og1 = og0 + 8 * HD;
    #pragma unroll
    for (int n = 0; n < 8; n++) {
        *(float2*)(og0 + n * 8 + cb) = make_float2(o[n][0] * inv0, o[n][1] * inv0);
        *(float2*)(og1 + n * 8 + cb) = make_float2(o[n][2] * inv1, o[n][3] * inv1);
    }
}

extern "C" void kernel_launch(void* const* d_in, const int* in_sizes, int n_in,
                              void* d_out, int out_size)
{
    const float* q = (const float*)d_in[0];
    const float* k = (const float*)d_in[1];
    const float* v = (const float*)d_in[2];
    float* o = (float*)d_out;

    int n_bh = in_sizes[0] / (SEQ * HD);    // 32

    cudaFuncSetAttribute(fa4_kernel, cudaFuncAttributeMaxDynamicSharedMemorySize,
                         SMEM_BYTES);

    cvt_kernel<<<(NTOT / 4 + 511) / 512, 512>>>(q, k, v);
    dim3 grid(SEQ / BM, n_bh);
    fa4_kernel<<<grid, NTHR, SMEM_BYTES>>>(o);
}

// round 6
// speedup vs baseline: 1.0506x; 1.0201x over previous
#include <cuda_runtime.h>
#include <cuda_bf16.h>
#include <cstdint>

// FlashAttention B=2,H=16,S=4096,D=64 fp32, non-causal.
// Reference's exact recurrence (block_max variant), BN=128 fixed, in order.
// mma.sync m16n8k16 bf16, 3-term hi/lo split (~fp32 accuracy), exp2 domain.
// BM=64 / 128 threads / 96KB smem -> 2 CTAs per SM (Q staged through V region).

#define SEQ   4096
#define HD    64
#define BM    64
#define BN    128
#define NTHR  128
#define NBLK  (SEQ / BN)
// (1/sqrt(64)) * log2(e): scores land in log2 domain, exp := ex2.approx
#define SCL2E 0.18033688011112042f

#define NTOT  (2 * 16 * SEQ * HD)

__device__ __nv_bfloat16 g_qh[NTOT];
__device__ __nv_bfloat16 g_ql[NTOT];
__device__ __nv_bfloat16 g_kh[NTOT];
__device__ __nv_bfloat16 g_kl[NTOT];
__device__ __nv_bfloat16 g_vh[NTOT];
__device__ __nv_bfloat16 g_vl[NTOT];

// ---------------- converter: fp32 -> bf16 hi/lo ----------------
__device__ __forceinline__ void split4(float4 t, float s,
                                       __nv_bfloat16* hp, __nv_bfloat16* lp)
{
    float x0 = t.x * s, x1 = t.y * s, x2 = t.z * s, x3 = t.w * s;
    __nv_bfloat16 h0 = __float2bfloat16_rn(x0);
    __nv_bfloat16 h1 = __float2bfloat16_rn(x1);
    __nv_bfloat16 h2 = __float2bfloat16_rn(x2);
    __nv_bfloat16 h3 = __float2bfloat16_rn(x3);
    __nv_bfloat16 l0 = __float2bfloat16_rn(x0 - __bfloat162float(h0));
    __nv_bfloat16 l1 = __float2bfloat16_rn(x1 - __bfloat162float(h1));
    __nv_bfloat16 l2 = __float2bfloat16_rn(x2 - __bfloat162float(h2));
    __nv_bfloat16 l3 = __float2bfloat16_rn(x3 - __bfloat162float(h3));
    __nv_bfloat162 hA; hA.x = h0; hA.y = h1;
    __nv_bfloat162 hB; hB.x = h2; hB.y = h3;
    __nv_bfloat162 lA; lA.x = l0; lA.y = l1;
    __nv_bfloat162 lB; lB.x = l2; lB.y = l3;
    *(uint2*)hp = make_uint2(*(uint32_t*)&hA, *(uint32_t*)&hB);
    *(uint2*)lp = make_uint2(*(uint32_t*)&lA, *(uint32_t*)&lB);
}

__global__ __launch_bounds__(512)
void cvt_kernel(const float* __restrict__ q,
                const float* __restrict__ k,
                const float* __restrict__ v)
{
    int i = blockIdx.x * blockDim.x + threadIdx.x;
    if (i >= NTOT / 4) return;
    split4(((const float4*)q)[i], SCL2E, g_qh + 4 * i, g_ql + 4 * i);
    split4(((const float4*)k)[i], 1.0f,  g_kh + 4 * i, g_kl + 4 * i);
    split4(((const float4*)v)[i], 1.0f,  g_vh + 4 * i, g_vl + 4 * i);
}

// ---------------- smem layout (byte offsets) ----------------
// K stage st: hi at O_K0+st*32768, lo at +16384.  V (and transient Q) at O_VH.
#define O_K0   0
#define O_VH   65536
#define O_VL   81920
#define SMEM_BYTES 98304      // 96KB -> 2 CTAs/SM

// swizzled byte offset of a 16B chunk (row, chunk in [0,8))
__device__ __forceinline__ uint32_t swz(uint32_t row, uint32_t ch)
{
    return (row * 8u + (ch ^ (row & 7u))) * 16u;
}

__device__ __forceinline__ void cp16(uint32_t dst, const void* src)
{
    asm volatile("cp.async.cg.shared.global [%0], [%1], 16;" :: "r"(dst), "l"(src));
}
__device__ __forceinline__ void cp_commit() { asm volatile("cp.async.commit_group;"); }
__device__ __forceinline__ void cp_wait0()  { asm volatile("cp.async.wait_group 0;"); }
__device__ __forceinline__ void cp_wait1()  { asm volatile("cp.async.wait_group 1;"); }

__device__ __forceinline__ void ldm_x4(uint32_t a, uint32_t* r)
{
    asm volatile("ldmatrix.sync.aligned.m8n8.x4.shared.b16 {%0,%1,%2,%3}, [%4];"
                 : "=r"(r[0]), "=r"(r[1]), "=r"(r[2]), "=r"(r[3]) : "r"(a));
}
__device__ __forceinline__ void ldm_x4t(uint32_t a, uint32_t* r)
{
    asm volatile("ldmatrix.sync.aligned.m8n8.x4.trans.shared.b16 {%0,%1,%2,%3}, [%4];"
                 : "=r"(r[0]), "=r"(r[1]), "=r"(r[2]), "=r"(r[3]) : "r"(a));
}
__device__ __forceinline__ void mma_bf16(float* c, const uint32_t* a,
                                         const uint32_t* b)
{
    asm volatile(
        "mma.sync.aligned.m16n8k16.row.col.f32.bf16.bf16.f32 "
        "{%0,%1,%2,%3}, {%4,%5,%6,%7}, {%8,%9}, {%0,%1,%2,%3};"
        : "+f"(c[0]), "+f"(c[1]), "+f"(c[2]), "+f"(c[3])
        : "r"(a[0]), "r"(a[1]), "r"(a[2]), "r"(a[3]), "r"(b[0]), "r"(b[1]));
}
__device__ __forceinline__ uint32_t pack2(float a, float b)
{
    __nv_bfloat162 t;
    t.x = __float2bfloat16_rn(a);
    t.y = __float2bfloat16_rn(b);
    return *(uint32_t*)&t;
}
__device__ __forceinline__ float ex2f(float x)
{
    float r; asm("ex2.approx.f32 %0, %1;" : "=f"(r) : "f"(x)); return r;
}

__global__ __launch_bounds__(NTHR, 2)
void fa5_kernel(float* __restrict__ out)
{
    extern __shared__ __align__(16) unsigned char smraw[];
    uint32_t sb = (uint32_t)__cvta_generic_to_shared(smraw);

    const int tid  = threadIdx.x;
    const int lane = tid & 31;
    const int w    = tid >> 5;          // 4 warps, rows w*16..w*16+15
    const int bh   = blockIdx.y;
    const int qb   = blockIdx.x;

    const size_t kvbase = (size_t)bh * SEQ * HD;

    auto tile_ld = [&](uint32_t dstb, const __nv_bfloat16* src) {
        #pragma unroll
        for (int i = 0; i < 8; i++) {           // 1024 chunks (16KB tile)
            int c = tid + i * NTHR;
            cp16(dstb + swz(c >> 3, c & 7), src + (size_t)(c >> 3) * HD + (c & 7) * 8);
        }
    };
    auto load_K = [&](int i) {
        size_t g = kvbase + (size_t)i * BN * HD;
        uint32_t ks = sb + O_K0 + (i & 1) * 32768;
        tile_ld(ks,         g_kh + g);
        tile_ld(ks + 16384, g_kl + g);
    };
    auto load_V = [&](int i) {
        size_t g = kvbase + (size_t)i * BN * HD;
        tile_ld(sb + O_VH, g_vh + g);
        tile_ld(sb + O_VL, g_vl + g);
    };

    // ---- prologue: Q staged through the V region ----
    {
        const __nv_bfloat16* qh = g_qh + ((size_t)bh * SEQ + (size_t)qb * BM) * HD;
        const __nv_bfloat16* ql = g_ql + ((size_t)bh * SEQ + (size_t)qb * BM) * HD;
        #pragma unroll
        for (int i = 0; i < 4; i++) {           // 512 chunks (Q tile 8KB each)
            int c = tid + i * NTHR;
            uint32_t d = swz(c >> 3, c & 7);
            const size_t g = (size_t)(c >> 3) * HD + (c & 7) * 8;
            cp16(sb + O_VH + d, qh + g);        // Q hi -> V hi region
            cp16(sb + O_VL + d, ql + g);        // Q lo -> V lo region
        }
    }
    load_K(0);
    cp_commit();                                // g0 = {Q, K0}
    load_K(1);
    cp_commit();                                // g1 = {K1}

    cp_wait1();                                 // g0 done (Q, K0)
    __syncthreads();

    // ---- persistent Q fragments (from the V region) ----
    uint32_t qfh[4][4], qfl[4][4];
    {
        int quad = lane >> 3, i = lane & 7;
        int row = w * 16 + (quad & 1) * 8 + i;
        #pragma unroll
        for (int t = 0; t < 4; t++) {
            uint32_t a = swz(row, 2 * t + (quad >> 1));
            ldm_x4(sb + O_VH + a, qfh[t]);
            ldm_x4(sb + O_VL + a, qfl[t]);
        }
    }
    __syncthreads();                            // all warps done reading Q
    load_V(0);
    cp_commit();                                // g2 = {V0}

    float o[8][4];
    #pragma unroll
    for (int n = 0; n < 8; n++)
        #pragma unroll
        for (int r = 0; r < 4; r++) o[n][r] = 0.f;
    float m0 = -1e30f, m1 = -1e30f, nr0 = 0.f, nr1 = 0.f;

    for (int blk = 0; blk < NBLK; blk++) {
        // blk=0: pending {K1, V0} -> need V0 => wait all.
        // blk>=1: pending {V(blk), K(blk+1)} (+older done) -> wait_group 1.
        if (blk == 0) cp_wait0(); else cp_wait1();
        __syncthreads();                         // K(blk), V(blk) visible

        uint32_t kh_b = sb + O_K0 + (blk & 1) * 32768;

        // ---- QK^T: 3-term bf16, ldmatrix.x4 over n-tile pairs ----
        float c[16][4];
        const int rowB = (lane & 7) + ((lane >> 4) << 3);
        const int chB  = (lane >> 3) & 1;
        #pragma unroll
        for (int j2 = 0; j2 < 8; j2++) {
            c[2*j2][0] = c[2*j2][1] = c[2*j2][2] = c[2*j2][3] = 0.f;
            c[2*j2+1][0] = c[2*j2+1][1] = c[2*j2+1][2] = c[2*j2+1][3] = 0.f;
            int row = 16 * j2 + rowB;
            #pragma unroll
            for (int t = 0; t < 4; t++) {
                uint32_t a = kh_b + swz(row, 2 * t + chB);
                uint32_t b4h[4], b4l[4];
                ldm_x4(a, b4h);
                ldm_x4(a + 16384, b4l);
                mma_bf16(c[2*j2],   qfh[t], b4h);
                mma_bf16(c[2*j2],   qfh[t], b4l);
                mma_bf16(c[2*j2],   qfl[t], b4h);
                mma_bf16(c[2*j2+1], qfh[t], b4h + 2);
                mma_bf16(c[2*j2+1], qfh[t], b4l + 2);
                mma_bf16(c[2*j2+1], qfl[t], b4h + 2);
            }
        }

        // ---- block max (reference recurrence, log2 domain) ----
        float mx0 = -1e30f, mx1 = -1e30f;
        #pragma unroll
        for (int j = 0; j < 16; j++) {
            mx0 = fmaxf(mx0, fmaxf(c[j][0], c[j][1]));
            mx1 = fmaxf(mx1, fmaxf(c[j][2], c[j][3]));
        }
        mx0 = fmaxf(mx0, __shfl_xor_sync(0xffffffffu, mx0, 1));
        mx0 = fmaxf(mx0, __shfl_xor_sync(0xffffffffu, mx0, 2));
        mx1 = fmaxf(mx1, __shfl_xor_sync(0xffffffffu, mx1, 1));
        mx1 = fmaxf(mx1, __shfl_xor_sync(0xffffffffu, mx1, 2));

        float nm0 = fmaxf(m0, mx0), nm1 = fmaxf(m1, mx1);
        float e0 = ex2f(m0 - nm0), e1 = ex2f(m1 - nm1);
        m0 = nm0; m1 = nm1;
        #pragma unroll
        for (int n = 0; n < 8; n++) {
            o[n][0] *= e0; o[n][1] *= e0;
            o[n][2] *= e1; o[n][3] *= e1;
        }

        // ---- chunked exp + pack + PV (overlaps MUFU/pack with HMMA) ----
        float rs0 = 0.f, rs1 = 0.f;
        const int vri = lane & 15;
        const int vch = lane >> 4;
        #pragma unroll
        for (int t = 0; t < 8; t++) {
            uint32_t pah[4], pal[4];
            #pragma unroll
            for (int h = 0; h < 2; h++) {
                int j = 2 * t + h;
                float x0 = ex2f(c[j][0] - mx0);
                float x1 = ex2f(c[j][1] - mx0);
                float x2 = ex2f(c[j][2] - mx1);
                float x3 = ex2f(c[j][3] - mx1);
                rs0 += x0 + x1;
                rs1 += x2 + x3;
                uint32_t h01 = pack2(x0, x1);
                uint32_t h23 = pack2(x2, x3);
                float h0 = __uint_as_float(h01 << 16);
                float h1 = __uint_as_float(h01 & 0xffff0000u);
                float h2 = __uint_as_float(h23 << 16);
                float h3 = __uint_as_float(h23 & 0xffff0000u);
                pah[2*h]   = h01;
                pah[2*h+1] = h23;
                pal[2*h]   = pack2(x0 - h0, x1 - h1);
                pal[2*h+1] = pack2(x2 - h2, x3 - h3);
            }
            int vrow = 16 * t + vri;
            #pragma unroll
            for (int np = 0; np < 4; np++) {
                uint32_t a = sb + O_VH + swz(vrow, 2 * np + vch);
                uint32_t v4h[4], v4l[4];
                ldm_x4t(a, v4h);
                ldm_x4t(a + 16384, v4l);
                mma_bf16(o[2*np],   pah, v4h);
                mma_bf16(o[2*np],   pah, v4l);
                mma_bf16(o[2*np],   pal, v4h);
                mma_bf16(o[2*np+1], pah, v4h + 2);
                mma_bf16(o[2*np+1], pah, v4l + 2);
                mma_bf16(o[2*np+1], pal, v4h + 2);
            }
        }
        rs0 += __shfl_xor_sync(0xffffffffu, rs0, 1);
        rs0 += __shfl_xor_sync(0xffffffffu, rs0, 2);
        rs1 += __shfl_xor_sync(0xffffffffu, rs1, 1);
        rs1 += __shfl_xor_sync(0xffffffffu, rs1, 2);
        nr0 = nr0 * e0 + rs0;
        nr1 = nr1 * e1 + rs1;

        // ---- prefetch: V(blk+1) [group A], K(blk+2) [group B] ----
        __syncthreads();                 // everyone done reading V / K stage
        if (blk + 1 < NBLK) load_V(blk + 1);
        cp_commit();                     // A_blk (always committed)
        if (blk + 2 < NBLK) load_K(blk + 2);
        cp_commit();                     // B_blk (always committed)
    }

    // ---- epilogue ----
    float inv0 = 1.f / (nr0 + 1e-6f);
    float inv1 = 1.f / (nr1 + 1e-6f);
    int r  = lane >> 2;
    int cb = (lane & 3) * 2;
    float* og0 = out + ((size_t)bh * SEQ + (size_t)qb * BM + w * 16 + r) * HD;
    float* og1 = og0 + 8 * HD;
    #pragma unroll
    for (int n = 0; n < 8; n++) {
        *(float2*)(og0 + n * 8 + cb) = make_float2(o[n][0] * inv0, o[n][1] * inv0);
        *(float2*)(og1 + n * 8 + cb) = make_float2(o[n][2] * inv1, o[n][3] * inv1);
    }
}

extern "C" void kernel_launch(void* const* d_in, const int* in_sizes, int n_in,
                              void* d_out, int out_size)
{
    const float* q = (const float*)d_in[0];
    const float* k = (const float*)d_in[1];
    const float* v = (const float*)d_in[2];
    float* o = (float*)d_out;

    int n_bh = in_sizes[0] / (SEQ * HD);    // 32

    cudaFuncSetAttribute(fa5_kernel, cudaFuncAttributeMaxDynamicSharedMemorySize,
                         SMEM_BYTES);

    cvt_kernel<<<(NTOT / 4 + 511) / 512, 512>>>(q, k, v);
    dim3 grid(SEQ / BM, n_bh);
    fa5_kernel<<<grid, NTHR, SMEM_BYTES>>>(o);
}

// round 7
// speedup vs baseline: 1.2517x; 1.1914x over previous
#include <cuda_runtime.h>
#include <cuda_bf16.h>
#include <cuda_fp16.h>
#include <cstdint>

// FlashAttention B=2,H=16,S=4096,D=64 fp32, non-causal.
// Reference's exact recurrence (block_max variant), BN=128 fixed, in order.
// QK^T: mma.sync bf16 3-term hi/lo split (err ~1e-5, feeds exp).
// PV:   mma.sync fp16, P single (P in (0,1], err 2^-12) x V hi/lo -> 2 MMAs.
// BM=64 / 128 threads / 96KB smem -> 2 CTAs per SM.

#define SEQ   4096
#define HD    64
#define BM    64
#define BN    128
#define NTHR  128
#define NBLK  (SEQ / BN)
// (1/sqrt(64)) * log2(e): scores land in log2 domain, exp := ex2.approx
#define SCL2E 0.18033688011112042f

#define NTOT  (2 * 16 * SEQ * HD)

__device__ __nv_bfloat16 g_qh[NTOT];
__device__ __nv_bfloat16 g_ql[NTOT];
__device__ __nv_bfloat16 g_kh[NTOT];
__device__ __nv_bfloat16 g_kl[NTOT];
__device__ __half        g_vh[NTOT];
__device__ __half        g_vl[NTOT];

// ---------------- converters ----------------
__device__ __forceinline__ void split4b(float4 t, float s,
                                        __nv_bfloat16* hp, __nv_bfloat16* lp)
{
    float x0 = t.x * s, x1 = t.y * s, x2 = t.z * s, x3 = t.w * s;
    __nv_bfloat16 h0 = __float2bfloat16_rn(x0);
    __nv_bfloat16 h1 = __float2bfloat16_rn(x1);
    __nv_bfloat16 h2 = __float2bfloat16_rn(x2);
    __nv_bfloat16 h3 = __float2bfloat16_rn(x3);
    __nv_bfloat16 l0 = __float2bfloat16_rn(x0 - __bfloat162float(h0));
    __nv_bfloat16 l1 = __float2bfloat16_rn(x1 - __bfloat162float(h1));
    __nv_bfloat16 l2 = __float2bfloat16_rn(x2 - __bfloat162float(h2));
    __nv_bfloat16 l3 = __float2bfloat16_rn(x3 - __bfloat162float(h3));
    __nv_bfloat162 hA; hA.x = h0; hA.y = h1;
    __nv_bfloat162 hB; hB.x = h2; hB.y = h3;
    __nv_bfloat162 lA; lA.x = l0; lA.y = l1;
    __nv_bfloat162 lB; lB.x = l2; lB.y = l3;
    *(uint2*)hp = make_uint2(*(uint32_t*)&hA, *(uint32_t*)&hB);
    *(uint2*)lp = make_uint2(*(uint32_t*)&lA, *(uint32_t*)&lB);
}

__device__ __forceinline__ void split4h(float4 t, __half* hp, __half* lp)
{
    __half h0 = __float2half_rn(t.x);
    __half h1 = __float2half_rn(t.y);
    __half h2 = __float2half_rn(t.z);
    __half h3 = __float2half_rn(t.w);
    __half l0 = __float2half_rn(t.x - __half2float(h0));
    __half l1 = __float2half_rn(t.y - __half2float(h1));
    __half l2 = __float2half_rn(t.z - __half2float(h2));
    __half l3 = __float2half_rn(t.w - __half2float(h3));
    __half2 hA; hA.x = h0; hA.y = h1;
    __half2 hB; hB.x = h2; hB.y = h3;
    __half2 lA; lA.x = l0; lA.y = l1;
    __half2 lB; lB.x = l2; lB.y = l3;
    *(uint2*)hp = make_uint2(*(uint32_t*)&hA, *(uint32_t*)&hB);
    *(uint2*)lp = make_uint2(*(uint32_t*)&lA, *(uint32_t*)&lB);
}

__global__ __launch_bounds__(512)
void cvt_kernel(const float* __restrict__ q,
                const float* __restrict__ k,
                const float* __restrict__ v)
{
    int i = blockIdx.x * blockDim.x + threadIdx.x;
    if (i >= NTOT / 4) return;
    split4b(((const float4*)q)[i], SCL2E, g_qh + 4 * i, g_ql + 4 * i);
    split4b(((const float4*)k)[i], 1.0f,  g_kh + 4 * i, g_kl + 4 * i);
    split4h(((const float4*)v)[i],        g_vh + 4 * i, g_vl + 4 * i);
}

// ---------------- smem layout (byte offsets) ----------------
// K stage st: hi at O_K0+st*32768, lo at +16384.  V (and transient Q) at O_VH.
#define O_K0   0
#define O_VH   65536
#define O_VL   81920
#define SMEM_BYTES 98304      // 96KB -> 2 CTAs/SM

// swizzled byte offset of a 16B chunk (row, chunk in [0,8))
__device__ __forceinline__ uint32_t swz(uint32_t row, uint32_t ch)
{
    return (row * 8u + (ch ^ (row & 7u))) * 16u;
}

__device__ __forceinline__ void cp16(uint32_t dst, const void* src)
{
    asm volatile("cp.async.cg.shared.global [%0], [%1], 16;" :: "r"(dst), "l"(src));
}
__device__ __forceinline__ void cp_commit() { asm volatile("cp.async.commit_group;"); }
__device__ __forceinline__ void cp_wait0()  { asm volatile("cp.async.wait_group 0;"); }
__device__ __forceinline__ void cp_wait1()  { asm volatile("cp.async.wait_group 1;"); }

__device__ __forceinline__ void ldm_x4(uint32_t a, uint32_t* r)
{
    asm volatile("ldmatrix.sync.aligned.m8n8.x4.shared.b16 {%0,%1,%2,%3}, [%4];"
                 : "=r"(r[0]), "=r"(r[1]), "=r"(r[2]), "=r"(r[3]) : "r"(a));
}
__device__ __forceinline__ void ldm_x4t(uint32_t a, uint32_t* r)
{
    asm volatile("ldmatrix.sync.aligned.m8n8.x4.trans.shared.b16 {%0,%1,%2,%3}, [%4];"
                 : "=r"(r[0]), "=r"(r[1]), "=r"(r[2]), "=r"(r[3]) : "r"(a));
}
__device__ __forceinline__ void mma_bf16(float* c, const uint32_t* a,
                                         const uint32_t* b)
{
    asm volatile(
        "mma.sync.aligned.m16n8k16.row.col.f32.bf16.bf16.f32 "
        "{%0,%1,%2,%3}, {%4,%5,%6,%7}, {%8,%9}, {%0,%1,%2,%3};"
        : "+f"(c[0]), "+f"(c[1]), "+f"(c[2]), "+f"(c[3])
        : "r"(a[0]), "r"(a[1]), "r"(a[2]), "r"(a[3]), "r"(b[0]), "r"(b[1]));
}
__device__ __forceinline__ void mma_fp16(float* c, const uint32_t* a,
                                         const uint32_t* b)
{
    asm volatile(
        "mma.sync.aligned.m16n8k16.row.col.f32.f16.f16.f32 "
        "{%0,%1,%2,%3}, {%4,%5,%6,%7}, {%8,%9}, {%0,%1,%2,%3};"
        : "+f"(c[0]), "+f"(c[1]), "+f"(c[2]), "+f"(c[3])
        : "r"(a[0]), "r"(a[1]), "r"(a[2]), "r"(a[3]), "r"(b[0]), "r"(b[1]));
}
__device__ __forceinline__ uint32_t pack2h(float a, float b)
{
    __half2 t;
    t.x = __float2half_rn(a);
    t.y = __float2half_rn(b);
    return *(uint32_t*)&t;
}
__device__ __forceinline__ float ex2f(float x)
{
    float r; asm("ex2.approx.f32 %0, %1;" : "=f"(r) : "f"(x)); return r;
}

__global__ __launch_bounds__(NTHR, 2)
void fa6_kernel(float* __restrict__ out)
{
    extern __shared__ __align__(16) unsigned char smraw[];
    uint32_t sb = (uint32_t)__cvta_generic_to_shared(smraw);

    const int tid  = threadIdx.x;
    const int lane = tid & 31;
    const int w    = tid >> 5;          // 4 warps, rows w*16..w*16+15
    const int bh   = blockIdx.y;
    const int qb   = blockIdx.x;

    const size_t kvbase = (size_t)bh * SEQ * HD;

    auto tile_ld = [&](uint32_t dstb, const char* srcb) {
        #pragma unroll
        for (int i = 0; i < 8; i++) {           // 1024 chunks (16KB tile)
            int c = tid + i * NTHR;
            cp16(dstb + swz(c >> 3, c & 7),
                 srcb + ((size_t)(c >> 3) * HD + (c & 7) * 8) * 2);
        }
    };
    auto load_K = [&](int i) {
        size_t g = (kvbase + (size_t)i * BN * HD) * 2;
        uint32_t ks = sb + O_K0 + (i & 1) * 32768;
        tile_ld(ks,         (const char*)g_kh + g);
        tile_ld(ks + 16384, (const char*)g_kl + g);
    };
    auto load_V = [&](int i) {
        size_t g = (kvbase + (size_t)i * BN * HD) * 2;
        tile_ld(sb + O_VH, (const char*)g_vh + g);
        tile_ld(sb + O_VL, (const char*)g_vl + g);
    };

    // ---- prologue: Q staged through the V region ----
    {
        const char* qh = (const char*)(g_qh + ((size_t)bh * SEQ + (size_t)qb * BM) * HD);
        const char* ql = (const char*)(g_ql + ((size_t)bh * SEQ + (size_t)qb * BM) * HD);
        #pragma unroll
        for (int i = 0; i < 4; i++) {           // 512 chunks (Q tile 8KB each)
            int c = tid + i * NTHR;
            uint32_t d = swz(c >> 3, c & 7);
            const size_t g = ((size_t)(c >> 3) * HD + (c & 7) * 8) * 2;
            cp16(sb + O_VH + d, qh + g);        // Q hi -> V hi region
            cp16(sb + O_VL + d, ql + g);        // Q lo -> V lo region
        }
    }
    load_K(0);
    cp_commit();                                // g0 = {Q, K0}
    load_K(1);
    cp_commit();                                // g1 = {K1}

    cp_wait1();                                 // g0 done (Q, K0)
    __syncthreads();

    // ---- persistent Q fragments (from the V region) ----
    uint32_t qfh[4][4], qfl[4][4];
    {
        int quad = lane >> 3, i = lane & 7;
        int row = w * 16 + (quad & 1) * 8 + i;
        #pragma unroll
        for (int t = 0; t < 4; t++) {
            uint32_t a = swz(row, 2 * t + (quad >> 1));
            ldm_x4(sb + O_VH + a, qfh[t]);
            ldm_x4(sb + O_VL + a, qfl[t]);
        }
    }
    __syncthreads();                            // all warps done reading Q
    load_V(0);
    cp_commit();                                // g2 = {V0}

    float o[8][4];
    #pragma unroll
    for (int n = 0; n < 8; n++)
        #pragma unroll
        for (int r = 0; r < 4; r++) o[n][r] = 0.f;
    float m0 = -1e30f, m1 = -1e30f, nr0 = 0.f, nr1 = 0.f;

    for (int blk = 0; blk < NBLK; blk++) {
        // blk=0: pending {K1, V0} -> need V0 => wait all.
        // blk>=1: pending {V(blk), K(blk+1)} -> wait_group 1.
        if (blk == 0) cp_wait0(); else cp_wait1();
        __syncthreads();                         // K(blk), V(blk) visible

        uint32_t kh_b = sb + O_K0 + (blk & 1) * 32768;

        // ---- QK^T: 3-term bf16, ldmatrix.x4 over n-tile pairs ----
        float c[16][4];
        const int rowB = (lane & 7) + ((lane >> 4) << 3);
        const int chB  = (lane >> 3) & 1;
        #pragma unroll
        for (int j2 = 0; j2 < 8; j2++) {
            c[2*j2][0] = c[2*j2][1] = c[2*j2][2] = c[2*j2][3] = 0.f;
            c[2*j2+1][0] = c[2*j2+1][1] = c[2*j2+1][2] = c[2*j2+1][3] = 0.f;
            int row = 16 * j2 + rowB;
            #pragma unroll
            for (int t = 0; t < 4; t++) {
                uint32_t a = kh_b + swz(row, 2 * t + chB);
                uint32_t b4h[4], b4l[4];
                ldm_x4(a, b4h);
                ldm_x4(a + 16384, b4l);
                mma_bf16(c[2*j2],   qfh[t], b4h);
                mma_bf16(c[2*j2],   qfh[t], b4l);
                mma_bf16(c[2*j2],   qfl[t], b4h);
                mma_bf16(c[2*j2+1], qfh[t], b4h + 2);
                mma_bf16(c[2*j2+1], qfh[t], b4l + 2);
                mma_bf16(c[2*j2+1], qfl[t], b4h + 2);
            }
        }

        // ---- block max (reference recurrence, log2 domain) ----
        float mx0 = -1e30f, mx1 = -1e30f;
        #pragma unroll
        for (int j = 0; j < 16; j++) {
            mx0 = fmaxf(mx0, fmaxf(c[j][0], c[j][1]));
            mx1 = fmaxf(mx1, fmaxf(c[j][2], c[j][3]));
        }
        mx0 = fmaxf(mx0, __shfl_xor_sync(0xffffffffu, mx0, 1));
        mx0 = fmaxf(mx0, __shfl_xor_sync(0xffffffffu, mx0, 2));
        mx1 = fmaxf(mx1, __shfl_xor_sync(0xffffffffu, mx1, 1));
        mx1 = fmaxf(mx1, __shfl_xor_sync(0xffffffffu, mx1, 2));

        float nm0 = fmaxf(m0, mx0), nm1 = fmaxf(m1, mx1);
        float e0 = ex2f(m0 - nm0), e1 = ex2f(m1 - nm1);
        m0 = nm0; m1 = nm1;
        #pragma unroll
        for (int n = 0; n < 8; n++) {
            o[n][0] *= e0; o[n][1] *= e0;
            o[n][2] *= e1; o[n][3] *= e1;
        }

        // ---- chunked exp + fp16 pack + PV (P single-term) ----
        float rs0 = 0.f, rs1 = 0.f;
        const int vri = lane & 15;
        const int vch = lane >> 4;
        #pragma unroll
        for (int t = 0; t < 8; t++) {
            uint32_t pah[4];
            #pragma unroll
            for (int h = 0; h < 2; h++) {
                int j = 2 * t + h;
                float x0 = ex2f(c[j][0] - mx0);
                float x1 = ex2f(c[j][1] - mx0);
                float x2 = ex2f(c[j][2] - mx1);
                float x3 = ex2f(c[j][3] - mx1);
                rs0 += x0 + x1;
                rs1 += x2 + x3;
                pah[2*h]   = pack2h(x0, x1);
                pah[2*h+1] = pack2h(x2, x3);
            }
            int vrow = 16 * t + vri;
            #pragma unroll
            for (int np = 0; np < 4; np++) {
                uint32_t a = sb + O_VH + swz(vrow, 2 * np + vch);
                uint32_t v4h[4], v4l[4];
                ldm_x4t(a, v4h);
                ldm_x4t(a + 16384, v4l);
                mma_fp16(o[2*np],   pah, v4h);
                mma_fp16(o[2*np],   pah, v4l);
                mma_fp16(o[2*np+1], pah, v4h + 2);
                mma_fp16(o[2*np+1], pah, v4l + 2);
            }
        }
        rs0 += __shfl_xor_sync(0xffffffffu, rs0, 1);
        rs0 += __shfl_xor_sync(0xffffffffu, rs0, 2);
        rs1 += __shfl_xor_sync(0xffffffffu, rs1, 1);
        rs1 += __shfl_xor_sync(0xffffffffu, rs1, 2);
        nr0 = nr0 * e0 + rs0;
        nr1 = nr1 * e1 + rs1;

        // ---- prefetch: V(blk+1) [group A], K(blk+2) [group B] ----
        __syncthreads();                 // everyone done reading V / K stage
        if (blk + 1 < NBLK) load_V(blk + 1);
        cp_commit();                     // A_blk (always committed)
        if (blk + 2 < NBLK) load_K(blk + 2);
        cp_commit();                     // B_blk (always committed)
    }

    // ---- epilogue ----
    float inv0 = 1.f / (nr0 + 1e-6f);
    float inv1 = 1.f / (nr1 + 1e-6f);
    int r  = lane >> 2;
    int cb = (lane & 3) * 2;
    float* og0 = out + ((size_t)bh * SEQ + (size_t)qb * BM + w * 16 + r) * HD;
    float* og1 = og0 + 8 * HD;
    #pragma unroll
    for (int n = 0; n < 8; n++) {
        *(float2*)(og0 + n * 8 + cb) = make_float2(o[n][0] * inv0, o[n][1] * inv0);
        *(float2*)(og1 + n * 8 + cb) = make_float2(o[n][2] * inv1, o[n][3] * inv1);
    }
}

extern "C" void kernel_launch(void* const* d_in, const int* in_sizes, int n_in,
                              void* d_out, int out_size)
{
    const float* q = (const float*)d_in[0];
    const float* k = (const float*)d_in[1];
    const float* v = (const float*)d_in[2];
    float* o = (float*)d_out;

    int n_bh = in_sizes[0] / (SEQ * HD);    // 32

    cudaFuncSetAttribute(fa6_kernel, cudaFuncAttributeMaxDynamicSharedMemorySize,
                         SMEM_BYTES);

    cvt_kernel<<<(NTOT / 4 + 511) / 512, 512>>>(q, k, v);
    dim3 grid(SEQ / BM, n_bh);
    fa6_kernel<<<grid, NTHR, SMEM_BYTES>>>(o);
}

// round 8
// speedup vs baseline: 1.7669x; 1.4116x over previous
#include <cuda_runtime.h>
#include <cuda_fp16.h>
#include <cstdint>

// FlashAttention B=2,H=16,S=4096,D=64 fp32, non-causal.
// Reference's exact recurrence (block_max variant), BN=128 fixed, in order.
// All-fp16 tensor path:
//   QK^T: Q single fp16 x K fp16 hi/lo -> 2 MMAs (err ~2.4e-4)
//   PV:   P single fp16 x V single fp16 -> 1 MMA (err ~3e-4 total w/ P)
// fp32 accumulate everywhere; exp2 domain. BM=64/128thr/80KB -> 2 CTAs/SM.

#define SEQ   4096
#define HD    64
#define BM    64
#define BN    128
#define NTHR  128
#define NBLK  (SEQ / BN)
// (1/sqrt(64)) * log2(e): scores in log2 domain, exp := ex2.approx
#define SCL2E 0.18033688011112042f

#define NTOT  (2 * 16 * SEQ * HD)

__device__ __half g_q[NTOT];
__device__ __half g_kh[NTOT];
__device__ __half g_kl[NTOT];
__device__ __half g_v[NTOT];

// ---------------- converter ----------------
__global__ __launch_bounds__(512)
void cvt_kernel(const float* __restrict__ q,
                const float* __restrict__ k,
                const float* __restrict__ v)
{
    int i = blockIdx.x * blockDim.x + threadIdx.x;
    if (i >= NTOT / 4) return;

    float4 tq = ((const float4*)q)[i];
    __half2 qa; qa.x = __float2half_rn(tq.x * SCL2E); qa.y = __float2half_rn(tq.y * SCL2E);
    __half2 qb; qb.x = __float2half_rn(tq.z * SCL2E); qb.y = __float2half_rn(tq.w * SCL2E);
    *(uint2*)(g_q + 4 * i) = make_uint2(*(uint32_t*)&qa, *(uint32_t*)&qb);

    float4 tk = ((const float4*)k)[i];
    __half h0 = __float2half_rn(tk.x), h1 = __float2half_rn(tk.y);
    __half h2 = __float2half_rn(tk.z), h3 = __float2half_rn(tk.w);
    __half l0 = __float2half_rn(tk.x - __half2float(h0));
    __half l1 = __float2half_rn(tk.y - __half2float(h1));
    __half l2 = __float2half_rn(tk.z - __half2float(h2));
    __half l3 = __float2half_rn(tk.w - __half2float(h3));
    __half2 hA; hA.x = h0; hA.y = h1;
    __half2 hB; hB.x = h2; hB.y = h3;
    __half2 lA; lA.x = l0; lA.y = l1;
    __half2 lB; lB.x = l2; lB.y = l3;
    *(uint2*)(g_kh + 4 * i) = make_uint2(*(uint32_t*)&hA, *(uint32_t*)&hB);
    *(uint2*)(g_kl + 4 * i) = make_uint2(*(uint32_t*)&lA, *(uint32_t*)&lB);

    float4 tv = ((const float4*)v)[i];
    __half2 va; va.x = __float2half_rn(tv.x); va.y = __float2half_rn(tv.y);
    __half2 vb; vb.x = __float2half_rn(tv.z); vb.y = __float2half_rn(tv.w);
    *(uint2*)(g_v + 4 * i) = make_uint2(*(uint32_t*)&va, *(uint32_t*)&vb);
}

// ---------------- smem layout (byte offsets) ----------------
// K stage st: hi at O_K0+st*32768, lo at +16384.  V (and transient Q) at O_V.
#define O_K0   0
#define O_V    65536
#define SMEM_BYTES 81920      // 80KB -> 2 CTAs/SM

// swizzled byte offset of a 16B chunk (row, chunk in [0,8))
__device__ __forceinline__ uint32_t swz(uint32_t row, uint32_t ch)
{
    return (row * 8u + (ch ^ (row & 7u))) * 16u;
}

__device__ __forceinline__ void cp16(uint32_t dst, const void* src)
{
    asm volatile("cp.async.cg.shared.global [%0], [%1], 16;" :: "r"(dst), "l"(src));
}
__device__ __forceinline__ void cp_commit() { asm volatile("cp.async.commit_group;"); }
__device__ __forceinline__ void cp_wait0()  { asm volatile("cp.async.wait_group 0;"); }
__device__ __forceinline__ void cp_wait1()  { asm volatile("cp.async.wait_group 1;"); }

__device__ __forceinline__ void ldm_x4(uint32_t a, uint32_t* r)
{
    asm volatile("ldmatrix.sync.aligned.m8n8.x4.shared.b16 {%0,%1,%2,%3}, [%4];"
                 : "=r"(r[0]), "=r"(r[1]), "=r"(r[2]), "=r"(r[3]) : "r"(a));
}
__device__ __forceinline__ void ldm_x4t(uint32_t a, uint32_t* r)
{
    asm volatile("ldmatrix.sync.aligned.m8n8.x4.trans.shared.b16 {%0,%1,%2,%3}, [%4];"
                 : "=r"(r[0]), "=r"(r[1]), "=r"(r[2]), "=r"(r[3]) : "r"(a));
}
__device__ __forceinline__ void mma_fp16(float* c, const uint32_t* a,
                                         const uint32_t* b)
{
    asm volatile(
        "mma.sync.aligned.m16n8k16.row.col.f32.f16.f16.f32 "
        "{%0,%1,%2,%3}, {%4,%5,%6,%7}, {%8,%9}, {%0,%1,%2,%3};"
        : "+f"(c[0]), "+f"(c[1]), "+f"(c[2]), "+f"(c[3])
        : "r"(a[0]), "r"(a[1]), "r"(a[2]), "r"(a[3]), "r"(b[0]), "r"(b[1]));
}
__device__ __forceinline__ uint32_t pack2h(float a, float b)
{
    __half2 t;
    t.x = __float2half_rn(a);
    t.y = __float2half_rn(b);
    return *(uint32_t*)&t;
}
__device__ __forceinline__ float ex2f(float x)
{
    float r; asm("ex2.approx.f32 %0, %1;" : "=f"(r) : "f"(x)); return r;
}

__global__ __launch_bounds__(NTHR, 2)
void fa7_kernel(float* __restrict__ out)
{
    extern __shared__ __align__(16) unsigned char smraw[];
    uint32_t sb = (uint32_t)__cvta_generic_to_shared(smraw);

    const int tid  = threadIdx.x;
    const int lane = tid & 31;
    const int w    = tid >> 5;          // 4 warps, rows w*16..w*16+15
    const int bh   = blockIdx.y;
    const int qb   = blockIdx.x;

    const size_t kvbase = (size_t)bh * SEQ * HD;

    auto tile_ld = [&](uint32_t dstb, const char* srcb) {
        #pragma unroll
        for (int i = 0; i < 8; i++) {           // 1024 chunks (16KB tile)
            int c = tid + i * NTHR;
            cp16(dstb + swz(c >> 3, c & 7),
                 srcb + ((size_t)(c >> 3) * HD + (c & 7) * 8) * 2);
        }
    };
    auto load_K = [&](int i) {
        size_t g = (kvbase + (size_t)i * BN * HD) * 2;
        uint32_t ks = sb + O_K0 + (i & 1) * 32768;
        tile_ld(ks,         (const char*)g_kh + g);
        tile_ld(ks + 16384, (const char*)g_kl + g);
    };
    auto load_V = [&](int i) {
        size_t g = (kvbase + (size_t)i * BN * HD) * 2;
        tile_ld(sb + O_V, (const char*)g_v + g);
    };

    // ---- prologue: Q staged through the V region ----
    {
        const char* qp = (const char*)(g_q + ((size_t)bh * SEQ + (size_t)qb * BM) * HD);
        #pragma unroll
        for (int i = 0; i < 4; i++) {           // 512 chunks (Q tile 8KB)
            int c = tid + i * NTHR;
            cp16(sb + O_V + swz(c >> 3, c & 7),
                 qp + ((size_t)(c >> 3) * HD + (c & 7) * 8) * 2);
        }
    }
    load_K(0);
    cp_commit();                                // g0 = {Q, K0}
    load_K(1);
    cp_commit();                                // g1 = {K1}

    cp_wait1();                                 // g0 done (Q, K0)
    __syncthreads();

    // ---- persistent Q fragments ----
    uint32_t qf[4][4];
    {
        int quad = lane >> 3, i = lane & 7;
        int row = w * 16 + (quad & 1) * 8 + i;
        #pragma unroll
        for (int t = 0; t < 4; t++)
            ldm_x4(sb + O_V + swz(row, 2 * t + (quad >> 1)), qf[t]);
    }
    __syncthreads();                            // all warps done reading Q
    load_V(0);
    cp_commit();                                // g2 = {V0}

    float o[8][4];
    #pragma unroll
    for (int n = 0; n < 8; n++)
        #pragma unroll
        for (int r = 0; r < 4; r++) o[n][r] = 0.f;
    float m0 = -1e30f, m1 = -1e30f, nr0 = 0.f, nr1 = 0.f;

    for (int blk = 0; blk < NBLK; blk++) {
        // blk=0: pending {K1, V0} -> wait all.  blk>=1: wait_group 1.
        if (blk == 0) cp_wait0(); else cp_wait1();
        __syncthreads();                         // K(blk), V(blk) visible

        uint32_t kh_b = sb + O_K0 + (blk & 1) * 32768;

        // ---- QK^T: Q single x K hi/lo = 2 MMAs per (j2,t,ntile) pair ----
        float c[16][4];
        const int rowB = (lane & 7) + ((lane >> 4) << 3);
        const int chB  = (lane >> 3) & 1;
        #pragma unroll
        for (int j2 = 0; j2 < 8; j2++) {
            c[2*j2][0] = c[2*j2][1] = c[2*j2][2] = c[2*j2][3] = 0.f;
            c[2*j2+1][0] = c[2*j2+1][1] = c[2*j2+1][2] = c[2*j2+1][3] = 0.f;
            int row = 16 * j2 + rowB;
            #pragma unroll
            for (int t = 0; t < 4; t++) {
                uint32_t a = kh_b + swz(row, 2 * t + chB);
                uint32_t b4h[4], b4l[4];
                ldm_x4(a, b4h);
                ldm_x4(a + 16384, b4l);
                mma_fp16(c[2*j2],   qf[t], b4h);
                mma_fp16(c[2*j2],   qf[t], b4l);
                mma_fp16(c[2*j2+1], qf[t], b4h + 2);
                mma_fp16(c[2*j2+1], qf[t], b4l + 2);
            }
        }

        // ---- block max (reference recurrence, log2 domain) ----
        float mx0 = -1e30f, mx1 = -1e30f;
        #pragma unroll
        for (int j = 0; j < 16; j++) {
            mx0 = fmaxf(mx0, fmaxf(c[j][0], c[j][1]));
            mx1 = fmaxf(mx1, fmaxf(c[j][2], c[j][3]));
        }
        mx0 = fmaxf(mx0, __shfl_xor_sync(0xffffffffu, mx0, 1));
        mx0 = fmaxf(mx0, __shfl_xor_sync(0xffffffffu, mx0, 2));
        mx1 = fmaxf(mx1, __shfl_xor_sync(0xffffffffu, mx1, 1));
        mx1 = fmaxf(mx1, __shfl_xor_sync(0xffffffffu, mx1, 2));

        float nm0 = fmaxf(m0, mx0), nm1 = fmaxf(m1, mx1);
        float e0 = ex2f(m0 - nm0), e1 = ex2f(m1 - nm1);
        m0 = nm0; m1 = nm1;
        #pragma unroll
        for (int n = 0; n < 8; n++) {
            o[n][0] *= e0; o[n][1] *= e0;
            o[n][2] *= e1; o[n][3] *= e1;
        }

        // ---- chunked exp + fp16 pack + PV (P single x V single) ----
        float rs0 = 0.f, rs1 = 0.f;
        const int vri = lane & 15;
        const int vch = lane >> 4;
        #pragma unroll
        for (int t = 0; t < 8; t++) {
            uint32_t pah[4];
            #pragma unroll
            for (int h = 0; h < 2; h++) {
                int j = 2 * t + h;
                float x0 = ex2f(c[j][0] - mx0);
                float x1 = ex2f(c[j][1] - mx0);
                float x2 = ex2f(c[j][2] - mx1);
                float x3 = ex2f(c[j][3] - mx1);
                rs0 += x0 + x1;
                rs1 += x2 + x3;
                pah[2*h]   = pack2h(x0, x1);
                pah[2*h+1] = pack2h(x2, x3);
            }
            int vrow = 16 * t + vri;
            #pragma unroll
            for (int np = 0; np < 4; np++) {
                uint32_t v4[4];
                ldm_x4t(sb + O_V + swz(vrow, 2 * np + vch), v4);
                mma_fp16(o[2*np],   pah, v4);
                mma_fp16(o[2*np+1], pah, v4 + 2);
            }
        }
        rs0 += __shfl_xor_sync(0xffffffffu, rs0, 1);
        rs0 += __shfl_xor_sync(0xffffffffu, rs0, 2);
        rs1 += __shfl_xor_sync(0xffffffffu, rs1, 1);
        rs1 += __shfl_xor_sync(0xffffffffu, rs1, 2);
        nr0 = nr0 * e0 + rs0;
        nr1 = nr1 * e1 + rs1;

        // ---- prefetch: V(blk+1) [group A], K(blk+2) [group B] ----
        __syncthreads();                 // everyone done reading V / K stage
        if (blk + 1 < NBLK) load_V(blk + 1);
        cp_commit();                     // A_blk (always committed)
        if (blk + 2 < NBLK) load_K(blk + 2);
        cp_commit();                     // B_blk (always committed)
    }

    // ---- epilogue ----
    float inv0 = 1.f / (nr0 + 1e-6f);
    float inv1 = 1.f / (nr1 + 1e-6f);
    int r  = lane >> 2;
    int cb = (lane & 3) * 2;
    float* og0 = out + ((size_t)bh * SEQ + (size_t)qb * BM + w * 16 + r) * HD;
    float* og1 = og0 + 8 * HD;
    #pragma unroll
    for (int n = 0; n < 8; n++) {
        *(float2*)(og0 + n * 8 + cb) = make_float2(o[n][0] * inv0, o[n][1] * inv0);
        *(float2*)(og1 + n * 8 + cb) = make_float2(o[n][2] * inv1, o[n][3] * inv1);
    }
}

extern "C" void kernel_launch(void* const* d_in, const int* in_sizes, int n_in,
                              void* d_out, int out_size)
{
    const float* q = (const float*)d_in[0];
    const float* k = (const float*)d_in[1];
    const float* v = (const float*)d_in[2];
    float* o = (float*)d_out;

    int n_bh = in_sizes[0] / (SEQ * HD);    // 32

    cudaFuncSetAttribute(fa7_kernel, cudaFuncAttributeMaxDynamicSharedMemorySize,
                         SMEM_BYTES);

    cvt_kernel<<<(NTOT / 4 + 511) / 512, 512>>>(q, k, v);
    dim3 grid(SEQ / BM, n_bh);
    fa7_kernel<<<grid, NTHR, SMEM_BYTES>>>(o);
}

// round 9
// speedup vs baseline: 2.2246x; 1.2590x over previous
#include <cuda_runtime.h>
#include <cuda_fp16.h>
#include <cstdint>

// FlashAttention B=2,H=16,S=4096,D=64 fp32, non-causal.
// Reference's exact recurrence (block_max variant), BN=128 fixed, in order.
// All-fp16 tensor path, fp32 accumulate:
//   QK^T: Q fp16 x K fp16 -> 1 MMA per tile  (err ~2x2.4e-4 RSS)
//   PV:   P fp16 x V fp16 -> 1 MMA per tile  (err ~1.8e-4 + 2.4e-4)
//   rowsum: P x all-ones B fragment -> same rescale recurrence as O.
// exp2 domain. BM=64 / 128 threads / 48KB smem -> 2 CTAs/SM.

#define SEQ   4096
#define HD    64
#define BM    64
#define BN    128
#define NTHR  128
#define NBLK  (SEQ / BN)
// (1/sqrt(64)) * log2(e): scores in log2 domain, exp := ex2.approx
#define SCL2E 0.18033688011112042f
#define ONES2 0x3C003C00u     // half2(1.0, 1.0)

#define NTOT  (2 * 16 * SEQ * HD)

__device__ __half g_q[NTOT];
__device__ __half g_k[NTOT];
__device__ __half g_v[NTOT];

// ---------------- converter ----------------
__global__ __launch_bounds__(512)
void cvt_kernel(const float* __restrict__ q,
                const float* __restrict__ k,
                const float* __restrict__ v)
{
    int i = blockIdx.x * blockDim.x + threadIdx.x;
    if (i >= NTOT / 4) return;

    float4 tq = ((const float4*)q)[i];
    __half2 qa; qa.x = __float2half_rn(tq.x * SCL2E); qa.y = __float2half_rn(tq.y * SCL2E);
    __half2 qb; qb.x = __float2half_rn(tq.z * SCL2E); qb.y = __float2half_rn(tq.w * SCL2E);
    *(uint2*)(g_q + 4 * i) = make_uint2(*(uint32_t*)&qa, *(uint32_t*)&qb);

    float4 tk = ((const float4*)k)[i];
    __half2 ka; ka.x = __float2half_rn(tk.x); ka.y = __float2half_rn(tk.y);
    __half2 kb; kb.x = __float2half_rn(tk.z); kb.y = __float2half_rn(tk.w);
    *(uint2*)(g_k + 4 * i) = make_uint2(*(uint32_t*)&ka, *(uint32_t*)&kb);

    float4 tv = ((const float4*)v)[i];
    __half2 va; va.x = __float2half_rn(tv.x); va.y = __float2half_rn(tv.y);
    __half2 vb; vb.x = __float2half_rn(tv.z); vb.y = __float2half_rn(tv.w);
    *(uint2*)(g_v + 4 * i) = make_uint2(*(uint32_t*)&va, *(uint32_t*)&vb);
}

// ---------------- smem layout (byte offsets) ----------------
// K stage st at O_K0 + st*16384.  V (and transient Q) at O_V.
#define O_K0   0
#define O_V    32768
#define SMEM_BYTES 49152      // 48KB -> 2 CTAs/SM (regs permitting)

// swizzled byte offset of a 16B chunk (row, chunk in [0,8))
__device__ __forceinline__ uint32_t swz(uint32_t row, uint32_t ch)
{
    return (row * 8u + (ch ^ (row & 7u))) * 16u;
}

__device__ __forceinline__ void cp16(uint32_t dst, const void* src)
{
    asm volatile("cp.async.cg.shared.global [%0], [%1], 16;" :: "r"(dst), "l"(src));
}
__device__ __forceinline__ void cp_commit() { asm volatile("cp.async.commit_group;"); }
__device__ __forceinline__ void cp_wait0()  { asm volatile("cp.async.wait_group 0;"); }
__device__ __forceinline__ void cp_wait1()  { asm volatile("cp.async.wait_group 1;"); }

__device__ __forceinline__ void ldm_x4(uint32_t a, uint32_t* r)
{
    asm volatile("ldmatrix.sync.aligned.m8n8.x4.shared.b16 {%0,%1,%2,%3}, [%4];"
                 : "=r"(r[0]), "=r"(r[1]), "=r"(r[2]), "=r"(r[3]) : "r"(a));
}
__device__ __forceinline__ void ldm_x4t(uint32_t a, uint32_t* r)
{
    asm volatile("ldmatrix.sync.aligned.m8n8.x4.trans.shared.b16 {%0,%1,%2,%3}, [%4];"
                 : "=r"(r[0]), "=r"(r[1]), "=r"(r[2]), "=r"(r[3]) : "r"(a));
}
__device__ __forceinline__ void mma_fp16(float* c, const uint32_t* a,
                                         const uint32_t* b)
{
    asm volatile(
        "mma.sync.aligned.m16n8k16.row.col.f32.f16.f16.f32 "
        "{%0,%1,%2,%3}, {%4,%5,%6,%7}, {%8,%9}, {%0,%1,%2,%3};"
        : "+f"(c[0]), "+f"(c[1]), "+f"(c[2]), "+f"(c[3])
        : "r"(a[0]), "r"(a[1]), "r"(a[2]), "r"(a[3]), "r"(b[0]), "r"(b[1]));
}
__device__ __forceinline__ uint32_t pack2h(float a, float b)
{
    __half2 t;
    t.x = __float2half_rn(a);
    t.y = __float2half_rn(b);
    return *(uint32_t*)&t;
}
__device__ __forceinline__ float ex2f(float x)
{
    float r; asm("ex2.approx.f32 %0, %1;" : "=f"(r) : "f"(x)); return r;
}

__global__ __launch_bounds__(NTHR, 2)
void fa8_kernel(float* __restrict__ out)
{
    extern __shared__ __align__(16) unsigned char smraw[];
    uint32_t sb = (uint32_t)__cvta_generic_to_shared(smraw);

    const int tid  = threadIdx.x;
    const int lane = tid & 31;
    const int w    = tid >> 5;          // 4 warps, rows w*16..w*16+15
    const int bh   = blockIdx.y;
    const int qb   = blockIdx.x;

    const size_t kvbase = (size_t)bh * SEQ * HD;

    auto tile_ld = [&](uint32_t dstb, const char* srcb) {
        #pragma unroll
        for (int i = 0; i < 8; i++) {           // 1024 chunks (16KB tile)
            int c = tid + i * NTHR;
            cp16(dstb + swz(c >> 3, c & 7),
                 srcb + ((size_t)(c >> 3) * HD + (c & 7) * 8) * 2);
        }
    };
    auto load_K = [&](int i) {
        tile_ld(sb + O_K0 + (i & 1) * 16384,
                (const char*)g_k + (kvbase + (size_t)i * BN * HD) * 2);
    };
    auto load_V = [&](int i) {
        tile_ld(sb + O_V,
                (const char*)g_v + (kvbase + (size_t)i * BN * HD) * 2);
    };

    // ---- prologue: Q staged through the V region ----
    {
        const char* qp = (const char*)(g_q + ((size_t)bh * SEQ + (size_t)qb * BM) * HD);
        #pragma unroll
        for (int i = 0; i < 4; i++) {           // 512 chunks (Q tile 8KB)
            int c = tid + i * NTHR;
            cp16(sb + O_V + swz(c >> 3, c & 7),
                 qp + ((size_t)(c >> 3) * HD + (c & 7) * 8) * 2);
        }
    }
    load_K(0);
    cp_commit();                                // g0 = {Q, K0}
    load_K(1);
    cp_commit();                                // g1 = {K1}

    cp_wait1();                                 // g0 done (Q, K0)
    __syncthreads();

    // ---- persistent Q fragments ----
    uint32_t qf[4][4];
    {
        int quad = lane >> 3, i = lane & 7;
        int row = w * 16 + (quad & 1) * 8 + i;
        #pragma unroll
        for (int t = 0; t < 4; t++)
            ldm_x4(sb + O_V + swz(row, 2 * t + (quad >> 1)), qf[t]);
    }
    __syncthreads();                            // all warps done reading Q
    load_V(0);
    cp_commit();                                // g2 = {V0}

    float o[8][4];
    #pragma unroll
    for (int n = 0; n < 8; n++)
        #pragma unroll
        for (int r = 0; r < 4; r++) o[n][r] = 0.f;
    float osum[4] = {0.f, 0.f, 0.f, 0.f};       // rowsum via ones-MMA
    float m0 = -1e30f, m1 = -1e30f;
    const uint32_t bones[2] = {ONES2, ONES2};

    for (int blk = 0; blk < NBLK; blk++) {
        // blk=0: pending {K1, V0} -> wait all.  blk>=1: wait_group 1.
        if (blk == 0) cp_wait0(); else cp_wait1();
        __syncthreads();                         // K(blk), V(blk) visible

        uint32_t kh_b = sb + O_K0 + (blk & 1) * 16384;

        // ---- QK^T: Q fp16 x K fp16, 1 MMA per (j2,t,ntile) ----
        float c[16][4];
        const int rowB = (lane & 7) + ((lane >> 4) << 3);
        const int chB  = (lane >> 3) & 1;
        #pragma unroll
        for (int j2 = 0; j2 < 8; j2++) {
            c[2*j2][0] = c[2*j2][1] = c[2*j2][2] = c[2*j2][3] = 0.f;
            c[2*j2+1][0] = c[2*j2+1][1] = c[2*j2+1][2] = c[2*j2+1][3] = 0.f;
            int row = 16 * j2 + rowB;
            #pragma unroll
            for (int t = 0; t < 4; t++) {
                uint32_t b4[4];
                ldm_x4(kh_b + swz(row, 2 * t + chB), b4);
                mma_fp16(c[2*j2],   qf[t], b4);
                mma_fp16(c[2*j2+1], qf[t], b4 + 2);
            }
        }

        // ---- block max (reference recurrence, log2 domain) ----
        float mx0 = -1e30f, mx1 = -1e30f;
        #pragma unroll
        for (int j = 0; j < 16; j++) {
            mx0 = fmaxf(mx0, fmaxf(c[j][0], c[j][1]));
            mx1 = fmaxf(mx1, fmaxf(c[j][2], c[j][3]));
        }
        mx0 = fmaxf(mx0, __shfl_xor_sync(0xffffffffu, mx0, 1));
        mx0 = fmaxf(mx0, __shfl_xor_sync(0xffffffffu, mx0, 2));
        mx1 = fmaxf(mx1, __shfl_xor_sync(0xffffffffu, mx1, 1));
        mx1 = fmaxf(mx1, __shfl_xor_sync(0xffffffffu, mx1, 2));

        float nm0 = fmaxf(m0, mx0), nm1 = fmaxf(m1, mx1);
        float e0 = ex2f(m0 - nm0), e1 = ex2f(m1 - nm1);
        m0 = nm0; m1 = nm1;
        #pragma unroll
        for (int n = 0; n < 8; n++) {
            o[n][0] *= e0; o[n][1] *= e0;
            o[n][2] *= e1; o[n][3] *= e1;
        }
        osum[0] *= e0; osum[1] *= e0;
        osum[2] *= e1; osum[3] *= e1;

        // ---- chunked exp + fp16 pack + PV + ones-MMA rowsum ----
        const int vri = lane & 15;
        const int vch = lane >> 4;
        #pragma unroll
        for (int t = 0; t < 8; t++) {
            uint32_t pah[4];
            #pragma unroll
            for (int h = 0; h < 2; h++) {
                int j = 2 * t + h;
                float x0 = ex2f(c[j][0] - mx0);
                float x1 = ex2f(c[j][1] - mx0);
                float x2 = ex2f(c[j][2] - mx1);
                float x3 = ex2f(c[j][3] - mx1);
                pah[2*h]   = pack2h(x0, x1);
                pah[2*h+1] = pack2h(x2, x3);
            }
            int vrow = 16 * t + vri;
            #pragma unroll
            for (int np = 0; np < 4; np++) {
                uint32_t v4[4];
                ldm_x4t(sb + O_V + swz(vrow, 2 * np + vch), v4);
                mma_fp16(o[2*np],   pah, v4);
                mma_fp16(o[2*np+1], pah, v4 + 2);
            }
            mma_fp16(osum, pah, bones);          // rowsum column
        }

        // ---- prefetch: V(blk+1) [group A], K(blk+2) [group B] ----
        __syncthreads();                 // everyone done reading V / K stage
        if (blk + 1 < NBLK) load_V(blk + 1);
        cp_commit();                     // A_blk (always committed)
        if (blk + 2 < NBLK) load_K(blk + 2);
        cp_commit();                     // B_blk (always committed)
    }

    // ---- epilogue: osum[0]=rowsum(r), osum[2]=rowsum(r+8) ----
    float inv0 = 1.f / (osum[0] + 1e-6f);
    float inv1 = 1.f / (osum[2] + 1e-6f);
    int r  = lane >> 2;
    int cb = (lane & 3) * 2;
    float* og0 = out + ((size_t)bh * SEQ + (size_t)qb * BM + w * 16 + r) * HD;
    float* og1 = og0 + 8 * HD;
    #pragma unroll
    for (int n = 0; n < 8; n++) {
        *(float2*)(og0 + n * 8 + cb) = make_float2(o[n][0] * inv0, o[n][1] * inv0);
        *(float2*)(og1 + n * 8 + cb) = make_float2(o[n][2] * inv1, o[n][3] * inv1);
    }
}

extern "C" void kernel_launch(void* const* d_in, const int* in_sizes, int n_in,
                              void* d_out, int out_size)
{
    const float* q = (const float*)d_in[0];
    const float* k = (const float*)d_in[1];
    const float* v = (const float*)d_in[2];
    float* o = (float*)d_out;

    int n_bh = in_sizes[0] / (SEQ * HD);    // 32

    cudaFuncSetAttribute(fa8_kernel, cudaFuncAttributeMaxDynamicSharedMemorySize,
                         SMEM_BYTES);

    cvt_kernel<<<(NTOT / 4 + 511) / 512, 512>>>(q, k, v);
    dim3 grid(SEQ / BM, n_bh);
    fa8_kernel<<<grid, NTHR, SMEM_BYTES>>>(o);
}

// round 10
// speedup vs baseline: 2.3942x; 1.0763x over previous
#include <cuda_runtime.h>
#include <cuda_fp16.h>
#include <cstdint>

// FlashAttention B=2,H=16,S=4096,D=64 fp32, non-causal.
// Reference's exact recurrence (block_max variant), BN=128 fixed, in order.
// All-fp16 tensor path, fp32 accumulate:
//   QK^T: Q fp16 x K fp16 -> 1 MMA/tile; PV: P fp16 x V fp16 -> 1 MMA/tile;
//   rowsum via all-ones B fragment (same rescale recurrence as O).
// Triple-buffered K/V (one __syncthreads per iter), warp-vote rescale skip.
// exp2 domain. BM=64 / 128 threads / 96KB smem -> 2 CTAs/SM.

#define SEQ   4096
#define HD    64
#define BM    64
#define BN    128
#define NTHR  128
#define NBLK  (SEQ / BN)
// (1/sqrt(64)) * log2(e): scores in log2 domain, exp := ex2.approx
#define SCL2E 0.18033688011112042f
#define ONES2 0x3C003C00u     // half2(1.0, 1.0)

#define NTOT  (2 * 16 * SEQ * HD)

__device__ __half g_q[NTOT];
__device__ __half g_k[NTOT];
__device__ __half g_v[NTOT];

// ---------------- converter ----------------
__global__ __launch_bounds__(512)
void cvt_kernel(const float* __restrict__ q,
                const float* __restrict__ k,
                const float* __restrict__ v)
{
    int i = blockIdx.x * blockDim.x + threadIdx.x;
    if (i >= NTOT / 4) return;

    float4 tq = ((const float4*)q)[i];
    __half2 qa = __floats2half2_rn(tq.x * SCL2E, tq.y * SCL2E);
    __half2 qb = __floats2half2_rn(tq.z * SCL2E, tq.w * SCL2E);
    *(uint2*)(g_q + 4 * i) = make_uint2(*(uint32_t*)&qa, *(uint32_t*)&qb);

    float4 tk = ((const float4*)k)[i];
    __half2 ka = __floats2half2_rn(tk.x, tk.y);
    __half2 kb = __floats2half2_rn(tk.z, tk.w);
    *(uint2*)(g_k + 4 * i) = make_uint2(*(uint32_t*)&ka, *(uint32_t*)&kb);

    float4 tv = ((const float4*)v)[i];
    __half2 va = __floats2half2_rn(tv.x, tv.y);
    __half2 vb = __floats2half2_rn(tv.z, tv.w);
    *(uint2*)(g_v + 4 * i) = make_uint2(*(uint32_t*)&va, *(uint32_t*)&vb);
}

// ---------------- smem layout (byte offsets) ----------------
// K slots: 0, 16384, 32768.  V slots: 49152, 65536, 81920.
#define O_K0   0
#define O_V0   49152
#define SMEM_BYTES 98304      // 96KB -> 2 CTAs/SM

// swizzled byte offset of a 16B chunk (row, chunk in [0,8))
__device__ __forceinline__ uint32_t swz(uint32_t row, uint32_t ch)
{
    return (row * 8u + (ch ^ (row & 7u))) * 16u;
}

__device__ __forceinline__ void cp16(uint32_t dst, const void* src)
{
    asm volatile("cp.async.cg.shared.global [%0], [%1], 16;" :: "r"(dst), "l"(src));
}
__device__ __forceinline__ void cp_commit() { asm volatile("cp.async.commit_group;"); }
__device__ __forceinline__ void cp_wait1()  { asm volatile("cp.async.wait_group 1;"); }

__device__ __forceinline__ void ldm_x4(uint32_t a, uint32_t* r)
{
    asm volatile("ldmatrix.sync.aligned.m8n8.x4.shared.b16 {%0,%1,%2,%3}, [%4];"
                 : "=r"(r[0]), "=r"(r[1]), "=r"(r[2]), "=r"(r[3]) : "r"(a));
}
__device__ __forceinline__ void ldm_x4t(uint32_t a, uint32_t* r)
{
    asm volatile("ldmatrix.sync.aligned.m8n8.x4.trans.shared.b16 {%0,%1,%2,%3}, [%4];"
                 : "=r"(r[0]), "=r"(r[1]), "=r"(r[2]), "=r"(r[3]) : "r"(a));
}
__device__ __forceinline__ void mma_fp16(float* c, const uint32_t* a,
                                         const uint32_t* b)
{
    asm volatile(
        "mma.sync.aligned.m16n8k16.row.col.f32.f16.f16.f32 "
        "{%0,%1,%2,%3}, {%4,%5,%6,%7}, {%8,%9}, {%0,%1,%2,%3};"
        : "+f"(c[0]), "+f"(c[1]), "+f"(c[2]), "+f"(c[3])
        : "r"(a[0]), "r"(a[1]), "r"(a[2]), "r"(a[3]), "r"(b[0]), "r"(b[1]));
}
__device__ __forceinline__ uint32_t pack2h(float a, float b)
{
    __half2 t = __floats2half2_rn(a, b);
    return *(uint32_t*)&t;
}
__device__ __forceinline__ float ex2f(float x)
{
    float r; asm("ex2.approx.f32 %0, %1;" : "=f"(r) : "f"(x)); return r;
}

__global__ __launch_bounds__(NTHR, 2)
void fa9_kernel(float* __restrict__ out)
{
    extern __shared__ __align__(16) unsigned char smraw[];
    uint32_t sb = (uint32_t)__cvta_generic_to_shared(smraw);

    const int tid  = threadIdx.x;
    const int lane = tid & 31;
    const int w    = tid >> 5;          // 4 warps, rows w*16..w*16+15
    const int bh   = blockIdx.y;
    const int qb   = blockIdx.x;

    const size_t kvbase = (size_t)bh * SEQ * HD;

    auto tile_ld = [&](uint32_t dstb, const char* srcb) {
        #pragma unroll
        for (int i = 0; i < 8; i++) {           // 1024 chunks (16KB tile)
            int c = tid + i * NTHR;
            cp16(dstb + swz(c >> 3, c & 7),
                 srcb + ((size_t)(c >> 3) * HD + (c & 7) * 8) * 2);
        }
    };
    auto load_K = [&](int i) {
        tile_ld(sb + O_K0 + (i % 3) * 16384,
                (const char*)g_k + (kvbase + (size_t)i * BN * HD) * 2);
    };
    auto load_V = [&](int i) {
        tile_ld(sb + O_V0 + (i % 3) * 16384,
                (const char*)g_v + (kvbase + (size_t)i * BN * HD) * 2);
    };

    // ---- prologue: Q staged through V slot 2 ----
    {
        const char* qp = (const char*)(g_q + ((size_t)bh * SEQ + (size_t)qb * BM) * HD);
        #pragma unroll
        for (int i = 0; i < 4; i++) {           // 512 chunks (Q tile 8KB)
            int c = tid + i * NTHR;
            cp16(sb + O_V0 + 2 * 16384 + swz(c >> 3, c & 7),
                 qp + ((size_t)(c >> 3) * HD + (c & 7) * 8) * 2);
        }
    }
    load_K(0); load_V(0);
    cp_commit();                                // g0 = {Q, K0, V0}
    load_K(1); load_V(1);
    cp_commit();                                // g1 = {K1, V1}

    cp_wait1();                                 // g0 done
    __syncthreads();

    // ---- persistent Q fragments (from V slot 2) ----
    uint32_t qf[4][4];
    {
        int quad = lane >> 3, i = lane & 7;
        int row = w * 16 + (quad & 1) * 8 + i;
        #pragma unroll
        for (int t = 0; t < 4; t++)
            ldm_x4(sb + O_V0 + 2 * 16384 + swz(row, 2 * t + (quad >> 1)), qf[t]);
    }

    float o[8][4];
    #pragma unroll
    for (int n = 0; n < 8; n++)
        #pragma unroll
        for (int r = 0; r < 4; r++) o[n][r] = 0.f;
    float osum[4] = {0.f, 0.f, 0.f, 0.f};       // rowsum via ones-MMA
    float m0 = -1e30f, m1 = -1e30f;
    const uint32_t bones[2] = {ONES2, ONES2};

    for (int blk = 0; blk < NBLK; blk++) {
        if (blk) cp_wait1();                     // K/V(blk) arrived
        __syncthreads();                         // + all warps done with blk-1
        // (sync also orders the Q ldmatrix reads before slot-2 overwrite below)

        // ---- prefetch blk+2 into slot (blk+2)%3 (freed by sync above) ----
        if (blk + 2 < NBLK) { load_K(blk + 2); load_V(blk + 2); }
        cp_commit();                             // one group per iter, always

        uint32_t kh_b = sb + O_K0 + (blk % 3) * 16384;
        uint32_t vh_b = sb + O_V0 + (blk % 3) * 16384;

        // ---- QK^T: Q fp16 x K fp16, 1 MMA per (j2,t,ntile) ----
        float c[16][4];
        const int rowB = (lane & 7) + ((lane >> 4) << 3);
        const int chB  = (lane >> 3) & 1;
        #pragma unroll
        for (int j2 = 0; j2 < 8; j2++) {
            c[2*j2][0] = c[2*j2][1] = c[2*j2][2] = c[2*j2][3] = 0.f;
            c[2*j2+1][0] = c[2*j2+1][1] = c[2*j2+1][2] = c[2*j2+1][3] = 0.f;
            int row = 16 * j2 + rowB;
            #pragma unroll
            for (int t = 0; t < 4; t++) {
                uint32_t b4[4];
                ldm_x4(kh_b + swz(row, 2 * t + chB), b4);
                mma_fp16(c[2*j2],   qf[t], b4);
                mma_fp16(c[2*j2+1], qf[t], b4 + 2);
            }
        }

        // ---- block max (reference recurrence, log2 domain) ----
        float mx0 = -1e30f, mx1 = -1e30f;
        #pragma unroll
        for (int j = 0; j < 16; j++) {
            mx0 = fmaxf(mx0, fmaxf(c[j][0], c[j][1]));
            mx1 = fmaxf(mx1, fmaxf(c[j][2], c[j][3]));
        }
        mx0 = fmaxf(mx0, __shfl_xor_sync(0xffffffffu, mx0, 1));
        mx0 = fmaxf(mx0, __shfl_xor_sync(0xffffffffu, mx0, 2));
        mx1 = fmaxf(mx1, __shfl_xor_sync(0xffffffffu, mx1, 1));
        mx1 = fmaxf(mx1, __shfl_xor_sync(0xffffffffu, mx1, 2));

        // vote-skip rescale: if no row in the warp has a new max, e==2^0==1
        // exactly and the rescale is a no-op (bitwise identical to doing it).
        if (__ballot_sync(0xffffffffu, (mx0 > m0) || (mx1 > m1))) {
            float nm0 = fmaxf(m0, mx0), nm1 = fmaxf(m1, mx1);
            float e0 = ex2f(m0 - nm0), e1 = ex2f(m1 - nm1);
            m0 = nm0; m1 = nm1;
            #pragma unroll
            for (int n = 0; n < 8; n++) {
                o[n][0] *= e0; o[n][1] *= e0;
                o[n][2] *= e1; o[n][3] *= e1;
            }
            osum[0] *= e0; osum[1] *= e0;
            osum[2] *= e1; osum[3] *= e1;
        }

        // ---- chunked exp + fp16 pack + PV + ones-MMA rowsum ----
        const int vri = lane & 15;
        const int vch = lane >> 4;
        #pragma unroll
        for (int t = 0; t < 8; t++) {
            uint32_t pah[4];
            #pragma unroll
            for (int h = 0; h < 2; h++) {
                int j = 2 * t + h;
                float x0 = ex2f(c[j][0] - mx0);
                float x1 = ex2f(c[j][1] - mx0);
                float x2 = ex2f(c[j][2] - mx1);
                float x3 = ex2f(c[j][3] - mx1);
                pah[2*h]   = pack2h(x0, x1);
                pah[2*h+1] = pack2h(x2, x3);
            }
            int vrow = 16 * t + vri;
            #pragma unroll
            for (int np = 0; np < 4; np++) {
                uint32_t v4[4];
                ldm_x4t(vh_b + swz(vrow, 2 * np + vch), v4);
                mma_fp16(o[2*np],   pah, v4);
                mma_fp16(o[2*np+1], pah, v4 + 2);
            }
            mma_fp16(osum, pah, bones);          // rowsum column
        }
    }

    // ---- epilogue: osum[0]=rowsum(r), osum[2]=rowsum(r+8) ----
    float inv0 = 1.f / (osum[0] + 1e-6f);
    float inv1 = 1.f / (osum[2] + 1e-6f);
    int r  = lane >> 2;
    int cb = (lane & 3) * 2;
    float* og0 = out + ((size_t)bh * SEQ + (size_t)qb * BM + w * 16 + r) * HD;
    float* og1 = og0 + 8 * HD;
    #pragma unroll
    for (int n = 0; n < 8; n++) {
        *(float2*)(og0 + n * 8 + cb) = make_float2(o[n][0] * inv0, o[n][1] * inv0);
        *(float2*)(og1 + n * 8 + cb) = make_float2(o[n][2] * inv1, o[n][3] * inv1);
    }
}

extern "C" void kernel_launch(void* const* d_in, const int* in_sizes, int n_in,
                              void* d_out, int out_size)
{
    const float* q = (const float*)d_in[0];
    const float* k = (const float*)d_in[1];
    const float* v = (const float*)d_in[2];
    float* o = (float*)d_out;

    int n_bh = in_sizes[0] / (SEQ * HD);    // 32

    cudaFuncSetAttribute(fa9_kernel, cudaFuncAttributeMaxDynamicSharedMemorySize,
                         SMEM_BYTES);

    cvt_kernel<<<(NTOT / 4 + 511) / 512, 512>>>(q, k, v);
    dim3 grid(SEQ / BM, n_bh);
    fa9_kernel<<<grid, NTHR, SMEM_BYTES>>>(o);
}